// round 2
// baseline (speedup 1.0000x reference)
#include <cuda_runtime.h>

typedef unsigned long long u64;
typedef unsigned int u32;

#define SEQ 512
#define BATCH 32
#define HID 1024
#define G4 4096
#define M_TOT 16384          /* SEQ*BATCH */
#define NB2 128              /* phase-2 persistent grid */
#define SMEM2 ((BATCH*HID + 64*33 + 512) * 4)

// scratch (device globals; no allocation allowed)
__device__ float g_xp[(size_t)2 * M_TOT * G4];      // [dir][s*32+b][gate]
__device__ float g_h[2 * 2 * BATCH * HID];          // [parity][dir][b][k]
__device__ u32 g_cnt;
__device__ u32 g_gen;

// ---------------- packed fp32x2 helpers (full-rate fp32 on sm_103a) -------
__device__ __forceinline__ u64 dupf(float a){u64 r;asm("mov.b64 %0,{%1,%1};":"=l"(r):"f"(a));return r;}
__device__ __forceinline__ u64 pk2(u32 a,u32 b){u64 r;asm("mov.b64 %0,{%1,%2};":"=l"(r):"r"(a),"r"(b));return r;}
__device__ __forceinline__ void fma2(u64 &d,u64 a,u64 b){asm("fma.rn.f32x2 %0,%1,%2,%0;":"+l"(d):"l"(a),"l"(b));}
__device__ __forceinline__ float2 unpk(u64 p){float2 f;asm("mov.b64 {%0,%1},%2;":"=f"(f.x),"=f"(f.y):"l"(p));return f;}
__device__ __forceinline__ float sigf(float x){return 1.0f/(1.0f+__expf(-x));}
__device__ __forceinline__ float4 ldcg4(const float* p){
    float4 v;asm volatile("ld.global.cg.v4.f32 {%0,%1,%2,%3},[%4];"
        :"=f"(v.x),"=f"(v.y),"=f"(v.z),"=f"(v.w):"l"(p));return v;}
__device__ __forceinline__ void stcg(float* p,float v){
    asm volatile("st.global.cg.f32 [%0],%1;"::"l"(p),"f"(v));}
__device__ __forceinline__ u32 ldgen(){
    u32 v;asm volatile("ld.global.cg.u32 %0,[%1];":"=r"(v):"l"(&g_gen));return v;}

// ---------------- grid barrier (generation-based, replay-safe) ------------
__device__ __forceinline__ void gridbar(){
    __syncthreads();
    if (threadIdx.x==0){
        u32 my = ldgen();
        __threadfence();
        if (atomicAdd(&g_cnt,1u) == NB2-1u){
            atomicExch(&g_cnt,0u);
            __threadfence();
            atomicExch(&g_gen, my+1u);
        } else {
            while (ldgen()==my) __nanosleep(64);
        }
        __threadfence();
    }
    __syncthreads();
}

// ---------------- phase 1: xp[d][s*32+b][g] = x_row . W^T + b -------------
// GEMM M=16384, N=4096, K=1024 per dir. 128x128 tile, BK=8, 8x8 micro.
__global__ __launch_bounds__(256) void xproj_kernel(
    const float* __restrict__ x,
    const float* __restrict__ Wf, const float* __restrict__ bf,
    const float* __restrict__ Wr, const float* __restrict__ br)
{
    const int d = blockIdx.z;
    const float* __restrict__ W    = d ? Wr : Wf;
    const float* __restrict__ bias = d ? br : bf;
    const int g0 = blockIdx.x << 7;
    const int m0 = blockIdx.y << 7;

    __shared__ __align__(16) float As[8][128];
    __shared__ __align__(16) float Bs[8][128];

    const int t    = threadIdx.x;
    const int lrow = t >> 1;
    const int lk4  = (t & 1) << 2;
    const int m    = m0 + lrow;
    const int s    = m >> 5, b = m & 31;
    const int srow = d ? (SEQ-1-s) : s;
    const float* aptr = x + ((size_t)b * SEQ + srow) * HID + lk4;
    const float* bptr = W + (size_t)(g0 + lrow) * HID + lk4;

    const int tx = t & 15, ty = t >> 4;
    const int cm = ty << 3, cg = tx << 3;

    u64 acc[8][4];
#pragma unroll
    for (int i=0;i<8;i++){
#pragma unroll
        for (int j=0;j<4;j++) acc[i][j]=0ull;
    }

    float4 av = *(const float4*)aptr;
    float4 bv = *(const float4*)bptr;

    for (int kb=0; kb<HID; kb+=8){
        __syncthreads();
        As[lk4+0][lrow]=av.x; As[lk4+1][lrow]=av.y;
        As[lk4+2][lrow]=av.z; As[lk4+3][lrow]=av.w;
        Bs[lk4+0][lrow]=bv.x; Bs[lk4+1][lrow]=bv.y;
        Bs[lk4+2][lrow]=bv.z; Bs[lk4+3][lrow]=bv.w;
        __syncthreads();
        if (kb+8 < HID){
            av = *(const float4*)(aptr + kb + 8);
            bv = *(const float4*)(bptr + kb + 8);
        }
#pragma unroll
        for (int k=0;k<8;k++){
            float4 a0 = *(const float4*)&As[k][cm];
            float4 a1 = *(const float4*)&As[k][cm+4];
            uint4  q0 = *(const uint4 *)&Bs[k][cg];
            uint4  q1 = *(const uint4 *)&Bs[k][cg+4];
            u64 ap[8] = { dupf(a0.x),dupf(a0.y),dupf(a0.z),dupf(a0.w),
                          dupf(a1.x),dupf(a1.y),dupf(a1.z),dupf(a1.w) };
            u64 bp[4] = { pk2(q0.x,q0.y), pk2(q0.z,q0.w),
                          pk2(q1.x,q1.y), pk2(q1.z,q1.w) };
#pragma unroll
            for (int i=0;i<8;i++){
#pragma unroll
                for (int j=0;j<4;j++) fma2(acc[i][j], ap[i], bp[j]);
            }
        }
    }

    float bb[8];
#pragma unroll
    for (int j=0;j<8;j++) bb[j]=bias[g0+cg+j];
#pragma unroll
    for (int i=0;i<8;i++){
        float* op = g_xp + ((size_t)d*M_TOT + (m0+cm+i))*G4 + g0+cg;
        float4 o0,o1; float2 p;
        p=unpk(acc[i][0]); o0.x=p.x+bb[0]; o0.y=p.y+bb[1];
        p=unpk(acc[i][1]); o0.z=p.x+bb[2]; o0.w=p.y+bb[3];
        p=unpk(acc[i][2]); o1.x=p.x+bb[4]; o1.y=p.y+bb[5];
        p=unpk(acc[i][3]); o1.z=p.x+bb[6]; o1.w=p.y+bb[7];
        *(float4*)op=o0; *(float4*)(op+4)=o1;
    }
}

// ---------------- phase 2: persistent recurrent kernel --------------------
// 128 CTAs = 2 dirs x 64. CTA owns 16 hidden units -> gate rows
// {q*1024 + j0 + u : q in 0..3, u in 0..15}. Per step: 32x64x1024 GEMM
// (f32x2 pairs along K), fused gates, c in smem, h double-buffered global.
__global__ __launch_bounds__(256,1) void lstm_kernel(
    const float* __restrict__ Whf, const float* __restrict__ Whr,
    float* __restrict__ out)
{
    extern __shared__ float smx[];
    float* hs   = smx;                  // 32*1024
    float* gbuf = smx + BATCH*HID;      // 64*33 (padded)
    float* cbuf = gbuf + 64*33;         // 512

    const int t   = threadIdx.x;
    const int cta = blockIdx.x;
    const int d   = cta >> 6;
    const int r   = cta & 63;
    const float* __restrict__ W = d ? Whr : Whf;
    const int j0 = r << 4;

    // zero h double-buffer (each CTA zeros its 1024-float slice) and c
    {
        float* p = g_h + cta*1024;
        for (int i=t;i<1024;i+=256) stcg(p+i, 0.0f);
    }
    cbuf[t]=0.0f; cbuf[t+256]=0.0f;
    __threadfence();
    gridbar();

    const int bg = t >> 4, rg = t & 15;
    const int q  = rg >> 2, u0 = (rg & 3) << 2;
    const int b0 = bg << 1;
    const float* Wb = W + (size_t)(q*HID + j0 + u0)*HID;
    const ulonglong2* W0 = (const ulonglong2*)(Wb);
    const ulonglong2* W1 = (const ulonglong2*)(Wb +   HID);
    const ulonglong2* W2 = (const ulonglong2*)(Wb + 2*HID);
    const ulonglong2* W3 = (const ulonglong2*)(Wb + 3*HID);

    for (int s=0; s<SEQ; s++){
        const int cur = s & 1, nxt = cur ^ 1;

        // stage h[cur][d] into smem (must bypass L1: written by other CTAs)
        {
            const float* hsrc = g_h + (cur*2 + d)*BATCH*HID;
            for (int i=t*4; i<BATCH*HID; i+=1024){
                float4 v = ldcg4(hsrc+i);
                *(float4*)(hs+i) = v;
            }
        }
        __syncthreads();

        // 64rows x 32batch x 1024 GEMM; thread tile 4 rows x 2 batches,
        // f32x2 pairs along K (no duplication movs).
        u64 acc[4][2];
#pragma unroll
        for (int i=0;i<4;i++){ acc[i][0]=0ull; acc[i][1]=0ull; }
        const ulonglong2* H0 = (const ulonglong2*)(hs +  b0   *HID);
        const ulonglong2* H1 = (const ulonglong2*)(hs + (b0+1)*HID);
#pragma unroll 4
        for (int c4=0;c4<HID/4;c4++){
            ulonglong2 wa=W0[c4], wb2=W1[c4], wc=W2[c4], wd=W3[c4];
            ulonglong2 ha=H0[c4], hb=H1[c4];
            fma2(acc[0][0],wa.x,ha.x);  fma2(acc[0][0],wa.y,ha.y);
            fma2(acc[0][1],wa.x,hb.x);  fma2(acc[0][1],wa.y,hb.y);
            fma2(acc[1][0],wb2.x,ha.x); fma2(acc[1][0],wb2.y,ha.y);
            fma2(acc[1][1],wb2.x,hb.x); fma2(acc[1][1],wb2.y,hb.y);
            fma2(acc[2][0],wc.x,ha.x);  fma2(acc[2][0],wc.y,ha.y);
            fma2(acc[2][1],wc.x,hb.x);  fma2(acc[2][1],wc.y,hb.y);
            fma2(acc[3][0],wd.x,ha.x);  fma2(acc[3][0],wd.y,ha.y);
            fma2(acc[3][1],wd.x,hb.x);  fma2(acc[3][1],wd.y,hb.y);
        }

        // add x-projection, stash gate pre-activations in smem
        {
            const float* xprow = g_xp + ((size_t)d*M_TOT + (size_t)s*BATCH)*G4;
#pragma unroll
            for (int i=0;i<4;i++){
                const int lr   = (rg<<2) + i;            // q*16+u0+i
                const int grow = q*HID + j0 + u0 + i;
#pragma unroll
                for (int jb=0;jb<2;jb++){
                    float2 p = unpk(acc[i][jb]);
                    float v = p.x + p.y + xprow[(size_t)(b0+jb)*G4 + grow];
                    gbuf[lr*33 + b0 + jb] = v;
                }
            }
        }
        __syncthreads();

        // fused LSTM cell update: 512 (unit,batch) pairs, 2 per thread
        const int sout = d ? (SEQ-1-s) : s;
#pragma unroll
        for (int e=0;e<2;e++){
            const int idx = t + e*256;
            const int u = idx >> 5, b = idx & 31;
            float iv = gbuf[( 0+u)*33+b];
            float fv = gbuf[(16+u)*33+b];
            float gv = gbuf[(32+u)*33+b];
            float ov = gbuf[(48+u)*33+b];
            float c  = cbuf[idx];
            c = sigf(fv)*c + sigf(iv)*tanhf(gv);
            float h = sigf(ov)*tanhf(c);
            cbuf[idx] = c;
            stcg(g_h + (nxt*2+d)*BATCH*HID + b*HID + (j0+u), h);
            out[((size_t)b*SEQ + sout)*(2*HID) + d*HID + (j0+u)] = h;
        }
        __threadfence();
        gridbar();
    }
}

// ---------------- launcher -------------------------------------------------
extern "C" void kernel_launch(void* const* d_in, const int* in_sizes, int n_in,
                              void* d_out, int out_size)
{
    const float* x    = (const float*)d_in[0];
    const float* Wii  = (const float*)d_in[1];
    const float* Whi  = (const float*)d_in[2];
    const float* bi   = (const float*)d_in[3];
    const float* WiiR = (const float*)d_in[4];
    const float* WhiR = (const float*)d_in[5];
    const float* biR  = (const float*)d_in[6];
    float* out = (float*)d_out;

    cudaFuncSetAttribute(lstm_kernel,
        cudaFuncAttributeMaxDynamicSharedMemorySize, SMEM2);

    dim3 g1(G4/128, M_TOT/128, 2);
    xproj_kernel<<<g1, 256>>>(x, Wii, bi, WiiR, biR);
    lstm_kernel<<<NB2, 256, SMEM2>>>(Whi, WhiR, out);
}

// round 3
// speedup vs baseline: 3.7693x; 3.7693x over previous
#include <cuda_runtime.h>

typedef unsigned long long u64;
typedef unsigned int u32;

#define SEQ 512
#define BATCH 32
#define HID 1024
#define G4 4096
#define M_TOT 16384          /* SEQ*BATCH */
#define NB2 128              /* phase-2 persistent grid */
#define KC 128               /* phase-2 W chunk depth */

/* phase-2 smem: hs4(128KB) + Ws double buffer(64KB) + gbuf + cbuf */
#define SM_HS4   (32768)
#define SM_WS    (2*64*KC)
#define SM_GB    (64*33)
#define SM_CB    (512)
#define SMEM2    ((SM_HS4 + SM_WS + SM_GB + SM_CB) * 4)

// scratch (device globals; no allocation allowed)
__device__ float g_xp[(size_t)2 * M_TOT * G4];      // [dir][s*32+b][gate]
__device__ float g_h[2 * 2 * BATCH * HID];          // [parity][dir][k4][b][4]
__device__ u32 g_cnt;
__device__ u32 g_gen;

// ---------------- packed fp32x2 helpers (full-rate fp32 on sm_103a) -------
__device__ __forceinline__ u64 dupf(float a){u64 r;asm("mov.b64 %0,{%1,%1};":"=l"(r):"f"(a));return r;}
__device__ __forceinline__ u64 pk2(u32 a,u32 b){u64 r;asm("mov.b64 %0,{%1,%2};":"=l"(r):"r"(a),"r"(b));return r;}
__device__ __forceinline__ void fma2(u64 &d,u64 a,u64 b){asm("fma.rn.f32x2 %0,%1,%2,%0;":"+l"(d):"l"(a),"l"(b));}
__device__ __forceinline__ float2 unpk(u64 p){float2 f;asm("mov.b64 {%0,%1},%2;":"=f"(f.x),"=f"(f.y):"l"(p));return f;}
__device__ __forceinline__ float sigf(float x){return 1.0f/(1.0f+__expf(-x));}
__device__ __forceinline__ float4 ldcg4(const float* p){
    float4 v;asm volatile("ld.global.cg.v4.f32 {%0,%1,%2,%3},[%4];"
        :"=f"(v.x),"=f"(v.y),"=f"(v.z),"=f"(v.w):"l"(p));return v;}
__device__ __forceinline__ float ldcg1(const float* p){
    float v;asm volatile("ld.global.cg.f32 %0,[%1];":"=f"(v):"l"(p));return v;}
__device__ __forceinline__ void stcg(float* p,float v){
    asm volatile("st.global.cg.f32 [%0],%1;"::"l"(p),"f"(v));}
__device__ __forceinline__ u32 ldgen(){
    u32 v;asm volatile("ld.global.cg.u32 %0,[%1];":"=r"(v):"l"(&g_gen));return v;}

// ---------------- grid barrier (generation-based, replay-safe) ------------
__device__ __forceinline__ void gridbar(){
    __syncthreads();
    if (threadIdx.x==0){
        u32 my = ldgen();
        __threadfence();
        if (atomicAdd(&g_cnt,1u) == NB2-1u){
            atomicExch(&g_cnt,0u);
            __threadfence();
            atomicExch(&g_gen, my+1u);
        } else {
            while (ldgen()==my) __nanosleep(64);
        }
        __threadfence();
    }
    __syncthreads();
}

// ---------------- phase 1: xp[d][s*32+b][g] = x_row . W^T + b -------------
__global__ __launch_bounds__(256) void xproj_kernel(
    const float* __restrict__ x,
    const float* __restrict__ Wf, const float* __restrict__ bf,
    const float* __restrict__ Wr, const float* __restrict__ br)
{
    const int d = blockIdx.z;
    const float* __restrict__ W    = d ? Wr : Wf;
    const float* __restrict__ bias = d ? br : bf;
    const int g0 = blockIdx.x << 7;
    const int m0 = blockIdx.y << 7;

    __shared__ __align__(16) float As[8][128];
    __shared__ __align__(16) float Bs[8][128];

    const int t    = threadIdx.x;
    const int lrow = t >> 1;
    const int lk4  = (t & 1) << 2;
    const int m    = m0 + lrow;
    const int s    = m >> 5, b = m & 31;
    const int srow = d ? (SEQ-1-s) : s;
    const float* aptr = x + ((size_t)b * SEQ + srow) * HID + lk4;
    const float* bptr = W + (size_t)(g0 + lrow) * HID + lk4;

    const int tx = t & 15, ty = t >> 4;
    const int cm = ty << 3, cg = tx << 3;

    u64 acc[8][4];
#pragma unroll
    for (int i=0;i<8;i++){
#pragma unroll
        for (int j=0;j<4;j++) acc[i][j]=0ull;
    }

    float4 av = *(const float4*)aptr;
    float4 bv = *(const float4*)bptr;

    for (int kb=0; kb<HID; kb+=8){
        __syncthreads();
        As[lk4+0][lrow]=av.x; As[lk4+1][lrow]=av.y;
        As[lk4+2][lrow]=av.z; As[lk4+3][lrow]=av.w;
        Bs[lk4+0][lrow]=bv.x; Bs[lk4+1][lrow]=bv.y;
        Bs[lk4+2][lrow]=bv.z; Bs[lk4+3][lrow]=bv.w;
        __syncthreads();
        if (kb+8 < HID){
            av = *(const float4*)(aptr + kb + 8);
            bv = *(const float4*)(bptr + kb + 8);
        }
#pragma unroll
        for (int k=0;k<8;k++){
            float4 a0 = *(const float4*)&As[k][cm];
            float4 a1 = *(const float4*)&As[k][cm+4];
            uint4  q0 = *(const uint4 *)&Bs[k][cg];
            uint4  q1 = *(const uint4 *)&Bs[k][cg+4];
            u64 ap[8] = { dupf(a0.x),dupf(a0.y),dupf(a0.z),dupf(a0.w),
                          dupf(a1.x),dupf(a1.y),dupf(a1.z),dupf(a1.w) };
            u64 bp[4] = { pk2(q0.x,q0.y), pk2(q0.z,q0.w),
                          pk2(q1.x,q1.y), pk2(q1.z,q1.w) };
#pragma unroll
            for (int i=0;i<8;i++){
#pragma unroll
                for (int j=0;j<4;j++) fma2(acc[i][j], ap[i], bp[j]);
            }
        }
    }

    float bb[8];
#pragma unroll
    for (int j=0;j<8;j++) bb[j]=bias[g0+cg+j];
#pragma unroll
    for (int i=0;i<8;i++){
        float* op = g_xp + ((size_t)d*M_TOT + (m0+cm+i))*G4 + g0+cg;
        float4 o0,o1; float2 p;
        p=unpk(acc[i][0]); o0.x=p.x+bb[0]; o0.y=p.y+bb[1];
        p=unpk(acc[i][1]); o0.z=p.x+bb[2]; o0.w=p.y+bb[3];
        p=unpk(acc[i][2]); o1.x=p.x+bb[4]; o1.y=p.y+bb[5];
        p=unpk(acc[i][3]); o1.z=p.x+bb[6]; o1.w=p.y+bb[7];
        *(float4*)op=o0; *(float4*)(op+4)=o1;
    }
}

// ---------------- phase 2: persistent recurrent kernel --------------------
// 128 CTAs = 2 dirs x 64. CTA owns 16 hidden units -> 64 gate rows
// {q*1024 + j0 + u}. Per step: G[64][32] = Wslice[64][1024] x h[1024][32].
// Warp w owns local rows w*8..w*8+7, lane = batch. W staged through smem
// (double-buffered 64xKC chunks, coalesced LDG + broadcast LDS). h staged
// as [k4][b][4] interleave so compute loads are contiguous LDS.128 / f32x2.
__global__ __launch_bounds__(256,1) void lstm_kernel(
    const float* __restrict__ Whf, const float* __restrict__ Whr,
    const float* __restrict__ out_dummy, float* __restrict__ out)
{
    extern __shared__ float smx[];
    float* hs4  = smx;                        // 32768 : [k4][b][4]
    float* Ws   = smx + SM_HS4;               // 2 x 64 x KC
    float* gbuf = Ws  + SM_WS;                // 64 x 33
    float* cbuf = gbuf + SM_GB;               // 512

    const int t   = threadIdx.x;
    const int cta = blockIdx.x;
    const int d   = cta >> 6;
    const int r   = cta & 63;
    const float* __restrict__ W = d ? Whr : Whf;
    const int j0 = r << 4;

    const int w  = t >> 5;         // warp 0..7
    const int ln = t & 31;         // lane = batch

    // zero h double-buffer slice + c
    {
        float* p = g_h + cta*1024;
        for (int i=t;i<1024;i+=256) stcg(p+i, 0.0f);
    }
    cbuf[t]=0.0f; cbuf[t+256]=0.0f;
    __threadfence();
    gridbar();

    // staging geometry: warp w stages local rows w*8+i ; lane covers k-span
    // local row ri -> global gate row grow(ri) = (ri>>4)*HID + j0 + (ri&15)
    const float* Wrow[8];
#pragma unroll
    for (int i=0;i<8;i++){
        int ri = w*8 + i;
        Wrow[i] = W + (size_t)((ri>>4)*HID + j0 + (ri&15))*HID;
    }

    for (int s=0; s<SEQ; s++){
        const int cur = s & 1, nxt = cur ^ 1;

        // ---- prefetch W chunk 0 into regs (hide L2 latency behind h copy)
        float4 wreg[8];
#pragma unroll
        for (int i=0;i<8;i++) wreg[i] = ldcg4(Wrow[i] + ln*4);

        // ---- prefetch xp rows for this step (used in epilogue)
        const float* xprow = g_xp + ((size_t)d*M_TOT + (size_t)s*BATCH)*G4;
        float xpv[8];
#pragma unroll
        for (int i=0;i<8;i++){
            int ri = w*8 + i;
            xpv[i] = ldcg1(xprow + (size_t)ln*G4 + (ri>>4)*HID + j0 + (ri&15));
        }

        // ---- stage h (straight 128KB coalesced copy; layout matches)
        {
            const float* hsrc = g_h + (cur*2 + d)*BATCH*HID;
            for (int i=t*4; i<BATCH*HID; i+=1024){
                float4 v = ldcg4(hsrc+i);
                *(float4*)(hs4+i) = v;
            }
        }

        // ---- store W chunk 0
        {
            float* dst = Ws + 0;   // buf 0
#pragma unroll
            for (int i=0;i<8;i++)
                *(float4*)(dst + (w*8+i)*KC + ln*4) = wreg[i];
        }
        __syncthreads();

        // ---- main K loop: 8 chunks of KC=128, double-buffered
        u64 acc[8];
#pragma unroll
        for (int i=0;i<8;i++) acc[i]=0ull;

        for (int c=0; c<HID/KC; c++){
            if (c+1 < HID/KC){
#pragma unroll
                for (int i=0;i<8;i++)
                    wreg[i] = ldcg4(Wrow[i] + (c+1)*KC + ln*4);
            }
            const float* WsC = Ws + (c&1)*64*KC + (w*8)*KC;
            const float* hsC = hs4 + c*KC*32;     // k4 base = c*32
#pragma unroll 4
            for (int k4=0; k4<KC/4; k4++){
                ulonglong2 h4 = *(const ulonglong2*)(hsC + (k4*32 + ln)*4);
#pragma unroll
                for (int i=0;i<8;i++){
                    ulonglong2 w4 = *(const ulonglong2*)(WsC + i*KC + k4*4);
                    fma2(acc[i], w4.x, h4.x);
                    fma2(acc[i], w4.y, h4.y);
                }
            }
            if (c+1 < HID/KC){
                float* dst = Ws + ((c+1)&1)*64*KC;
#pragma unroll
                for (int i=0;i<8;i++)
                    *(float4*)(dst + (w*8+i)*KC + ln*4) = wreg[i];
            }
            __syncthreads();
        }

        // ---- reduce + add xp, stash gate pre-activations
#pragma unroll
        for (int i=0;i<8;i++){
            float2 p = unpk(acc[i]);
            gbuf[(w*8+i)*33 + ln] = p.x + p.y + xpv[i];
        }
        __syncthreads();

        // ---- fused LSTM cell update: 512 (u,b) pairs, 2 per thread
        const int sout = d ? (SEQ-1-s) : s;
        float* hdst = g_h + (nxt*2+d)*BATCH*HID;
#pragma unroll
        for (int e=0;e<2;e++){
            const int p  = t + e*256;
            const int u  = p & 15, b = p >> 4;
            float iv = gbuf[( 0+u)*33+b];
            float fv = gbuf[(16+u)*33+b];
            float gv = gbuf[(32+u)*33+b];
            float ov = gbuf[(48+u)*33+b];
            float c  = cbuf[p];
            c = sigf(fv)*c + sigf(iv)*tanhf(gv);
            float h = sigf(ov)*tanhf(c);
            cbuf[p] = c;
            const int ug = j0 + u;
            stcg(hdst + (ug>>2)*128 + b*4 + (ug&3), h);
            out[((size_t)b*SEQ + sout)*(2*HID) + d*HID + ug] = h;
        }
        __threadfence();
        gridbar();
    }
}

// ---------------- launcher -------------------------------------------------
extern "C" void kernel_launch(void* const* d_in, const int* in_sizes, int n_in,
                              void* d_out, int out_size)
{
    const float* x    = (const float*)d_in[0];
    const float* Wii  = (const float*)d_in[1];
    const float* Whi  = (const float*)d_in[2];
    const float* bi   = (const float*)d_in[3];
    const float* WiiR = (const float*)d_in[4];
    const float* WhiR = (const float*)d_in[5];
    const float* biR  = (const float*)d_in[6];
    float* out = (float*)d_out;

    cudaFuncSetAttribute(lstm_kernel,
        cudaFuncAttributeMaxDynamicSharedMemorySize, SMEM2);

    dim3 g1(G4/128, M_TOT/128, 2);
    xproj_kernel<<<g1, 256>>>(x, Wii, bi, WiiR, biR);
    lstm_kernel<<<NB2, 256, SMEM2>>>(Whi, WhiR, nullptr, out);
}

// round 5
// speedup vs baseline: 8.6485x; 2.2945x over previous
#include <cuda_runtime.h>
#include <cuda_fp16.h>

typedef unsigned long long u64;
typedef unsigned int u32;

#define SEQ 512
#define BATCH 32
#define HID 1024
#define G4 4096
#define M_TOT 16384          /* SEQ*BATCH */
#define NB2 128              /* phase-2 persistent grid: 2 dirs x 64 */

#define WPAD 1048            /* padded row length (halves): 2096B stride */
#define WSLAB (64*WPAD)      /* 67072 halves = 134144 B */
#define HSLAB (32*WPAD)      /* 33536 halves =  67072 B */

/* lstm smem byte offsets */
#define OFF_MB 0             /* 2 mbarriers */
#define OFF_W  1024
#define OFF_H  (OFF_W + 64*WPAD*2)       /* +134144 */
#define OFF_GB (OFF_H + 32*WPAD*2)       /* +67072  : gbuf 64x34 fp32 */
#define OFF_CB (OFF_GB + 64*34*4)
#define SMEM2L (OFF_CB + 512*4)

// scratch (device globals; no allocation allowed)
__device__ float  g_xp[(size_t)2 * M_TOT * G4];     // [dir][s*32+b][gate] fp32
__device__ __half g_wh16[(size_t)128 * WSLAB];      // per-CTA padded W slabs
__device__ __half g_h16[4 * HSLAB];                 // [parity*2+dir][b][WPAD]
__device__ u32 g_cnt;
__device__ u32 g_gen;

// ---------------- small helpers -------------------------------------------
__device__ __forceinline__ u64 dupf(float a){u64 r;asm("mov.b64 %0,{%1,%1};":"=l"(r):"f"(a));return r;}
__device__ __forceinline__ u64 pk2(u32 a,u32 b){u64 r;asm("mov.b64 %0,{%1,%2};":"=l"(r):"r"(a),"r"(b));return r;}
__device__ __forceinline__ void fma2(u64 &d,u64 a,u64 b){asm("fma.rn.f32x2 %0,%1,%2,%0;":"+l"(d):"l"(a),"l"(b));}
__device__ __forceinline__ float2 unpk(u64 p){float2 f;asm("mov.b64 {%0,%1},%2;":"=f"(f.x),"=f"(f.y):"l"(p));return f;}
__device__ __forceinline__ float sigf(float x){return 1.0f/(1.0f+__expf(-x));}
__device__ __forceinline__ float ldcg1(const float* p){
    float v;asm volatile("ld.global.cg.f32 %0,[%1];":"=f"(v):"l"(p));return v;}
__device__ __forceinline__ void stcg_u32(u32* p,u32 v){
    asm volatile("st.global.cg.u32 [%0],%1;"::"l"(p),"r"(v));}
__device__ __forceinline__ void stcg16(void* p,unsigned short v){
    asm volatile("st.global.cg.u16 [%0],%1;"::"l"(p),"h"(v));}
__device__ __forceinline__ u32 ldgen(){
    u32 v;asm volatile("ld.global.cg.u32 %0,[%1];":"=r"(v):"l"(&g_gen));return v;}
__device__ __forceinline__ u32 smem_u32(const void* p){
    u32 a;asm("{ .reg .u64 t; cvta.to.shared.u64 t, %1; cvt.u32.u64 %0, t; }":"=r"(a):"l"(p));return a;}

// ---------------- mbarrier / bulk (base ISA, verified to compile) ---------
#define MINIT(mb,cnt) asm volatile("mbarrier.init.shared.b64 [%0], %1;"::"r"(mb),"r"(cnt):"memory")
#define MEXPECT(mb,tx) asm volatile("mbarrier.arrive.expect_tx.shared.b64 _, [%0], %1;"::"r"(mb),"r"(tx):"memory")
#define MWAIT(mb,ph) do{ asm volatile("{\n\t.reg .pred P1;\n\tWL%=:\n\t" \
    "mbarrier.try_wait.parity.acquire.cta.shared::cta.b64 P1, [%0], %1, 0x989680;\n\t" \
    "@P1 bra WD%=;\n\tbra WL%=;\n\tWD%=:\n\t}" :: "r"(mb), "r"(ph) : "memory"); }while(0)
#define BULK_G2S(sm,gp,sz,mb) asm volatile( \
    "cp.async.bulk.shared::cta.global.mbarrier::complete_tx::bytes [%0], [%1], %2, [%3];" \
    ::"r"(sm),"l"(gp),"r"(sz),"r"(mb):"memory")

__device__ __forceinline__ void ldsm4(u32& r0,u32& r1,u32& r2,u32& r3,u32 a){
    asm volatile("ldmatrix.sync.aligned.m8n8.x4.shared.b16 {%0,%1,%2,%3},[%4];"
        :"=r"(r0),"=r"(r1),"=r"(r2),"=r"(r3):"r"(a));
}
__device__ __forceinline__ void mma16816(float* c,u32 a0,u32 a1,u32 a2,u32 a3,u32 b0,u32 b1){
    asm volatile("mma.sync.aligned.m16n8k16.row.col.f32.f16.f16.f32 "
        "{%0,%1,%2,%3},{%4,%5,%6,%7},{%8,%9},{%0,%1,%2,%3};"
        :"+f"(c[0]),"+f"(c[1]),"+f"(c[2]),"+f"(c[3])
        :"r"(a0),"r"(a1),"r"(a2),"r"(a3),"r"(b0),"r"(b1));
}

// ---------------- grid barrier (generation-based, replay-safe) ------------
__device__ __forceinline__ void gridbar(){
    __syncthreads();
    if (threadIdx.x==0){
        u32 my = ldgen();
        __threadfence();
        if (atomicAdd(&g_cnt,1u) == NB2-1u){
            atomicExch(&g_cnt,0u);
            __threadfence();
            atomicExch(&g_gen, my+1u);
        } else {
            while (ldgen()==my) __nanosleep(64);
        }
        __threadfence();
    }
    __syncthreads();
}

// ---------------- phase 0: W_hi -> fp16 padded per-CTA slabs --------------
// cta c (d=c>>6, r=c&63, j0=r*16): local row ri 0..63 -> gate row
// grow = (ri>>4)*1024 + j0 + (ri&15); slab row stride WPAD halves.
__global__ __launch_bounds__(256) void wprep_kernel(
    const float* __restrict__ Whf, const float* __restrict__ Whr)
{
    const int c = blockIdx.x;
    const int d = c>>6, r = c&63, j0 = r<<4;
    const float* __restrict__ W = d ? Whr : Whf;
    __half* slab = g_wh16 + (size_t)c*WSLAB;

    const int t  = threadIdx.x;
    const int ri = t >> 2;
    const int k0 = (t & 3) << 8;
    const int grow = (ri>>4)*HID + j0 + (ri&15);
    const float* src = W + (size_t)grow*HID + k0;
    u32* dst = (u32*)(slab + ri*WPAD + k0);

#pragma unroll 8
    for (int k=0;k<256;k+=4){
        float4 v = *(const float4*)(src + k);
        __half2 h0 = __floats2half2_rn(v.x, v.y);
        __half2 h1 = __floats2half2_rn(v.z, v.w);
        dst[(k>>1)  ] = *(u32*)&h0;
        dst[(k>>1)+1] = *(u32*)&h1;
    }
}

// ---------------- phase 1: xp[d][s*32+b][g] = x_row . W^T + b (fp32) ------
__global__ __launch_bounds__(256) void xproj_kernel(
    const float* __restrict__ x,
    const float* __restrict__ Wf, const float* __restrict__ bf,
    const float* __restrict__ Wr, const float* __restrict__ br)
{
    const int d = blockIdx.z;
    const float* __restrict__ W    = d ? Wr : Wf;
    const float* __restrict__ bias = d ? br : bf;
    const int g0 = blockIdx.x << 7;
    const int m0 = blockIdx.y << 7;

    __shared__ __align__(16) float As[8][128];
    __shared__ __align__(16) float Bs[8][128];

    const int t    = threadIdx.x;
    const int lrow = t >> 1;
    const int lk4  = (t & 1) << 2;
    const int m    = m0 + lrow;
    const int s    = m >> 5, b = m & 31;
    const int srow = d ? (SEQ-1-s) : s;
    const float* aptr = x + ((size_t)b * SEQ + srow) * HID + lk4;
    const float* bptr = W + (size_t)(g0 + lrow) * HID + lk4;

    const int tx = t & 15, ty = t >> 4;
    const int cm = ty << 3, cg = tx << 3;

    u64 acc[8][4];
#pragma unroll
    for (int i=0;i<8;i++){
#pragma unroll
        for (int j=0;j<4;j++) acc[i][j]=0ull;
    }

    float4 av = *(const float4*)aptr;
    float4 bv = *(const float4*)bptr;

    for (int kb=0; kb<HID; kb+=8){
        __syncthreads();
        As[lk4+0][lrow]=av.x; As[lk4+1][lrow]=av.y;
        As[lk4+2][lrow]=av.z; As[lk4+3][lrow]=av.w;
        Bs[lk4+0][lrow]=bv.x; Bs[lk4+1][lrow]=bv.y;
        Bs[lk4+2][lrow]=bv.z; Bs[lk4+3][lrow]=bv.w;
        __syncthreads();
        if (kb+8 < HID){
            av = *(const float4*)(aptr + kb + 8);
            bv = *(const float4*)(bptr + kb + 8);
        }
#pragma unroll
        for (int k=0;k<8;k++){
            float4 a0 = *(const float4*)&As[k][cm];
            float4 a1 = *(const float4*)&As[k][cm+4];
            uint4  q0 = *(const uint4 *)&Bs[k][cg];
            uint4  q1 = *(const uint4 *)&Bs[k][cg+4];
            u64 ap[8] = { dupf(a0.x),dupf(a0.y),dupf(a0.z),dupf(a0.w),
                          dupf(a1.x),dupf(a1.y),dupf(a1.z),dupf(a1.w) };
            u64 bp[4] = { pk2(q0.x,q0.y), pk2(q0.z,q0.w),
                          pk2(q1.x,q1.y), pk2(q1.z,q1.w) };
#pragma unroll
            for (int i=0;i<8;i++){
#pragma unroll
                for (int j=0;j<4;j++) fma2(acc[i][j], ap[i], bp[j]);
            }
        }
    }

    float bb[8];
#pragma unroll
    for (int j=0;j<8;j++) bb[j]=bias[g0+cg+j];
#pragma unroll
    for (int i=0;i<8;i++){
        float* op = g_xp + ((size_t)d*M_TOT + (m0+cm+i))*G4 + g0+cg;
        float4 o0,o1; float2 p;
        p=unpk(acc[i][0]); o0.x=p.x+bb[0]; o0.y=p.y+bb[1];
        p=unpk(acc[i][1]); o0.z=p.x+bb[2]; o0.w=p.y+bb[3];
        p=unpk(acc[i][2]); o1.x=p.x+bb[4]; o1.y=p.y+bb[5];
        p=unpk(acc[i][3]); o1.z=p.x+bb[6]; o1.w=p.y+bb[7];
        *(float4*)op=o0; *(float4*)(op+4)=o1;
    }
}

// ---------------- phase 2: persistent mma.sync recurrent kernel -----------
// 128 CTAs = 2 dirs x 64. CTA owns 16 hidden units -> 64 gate rows.
// W slab (fp16, 134KB) resident in smem for all 512 steps (loaded once).
// Per step: h bulk copy (67KB) -> G[64][32] = W @ h^T via mma.m16n8k16
// (warp = 16 rows x 16 batches) -> fused gates -> c (smem), h (global fp16).
__global__ __launch_bounds__(256,1) void lstm_kernel(float* __restrict__ out)
{
    extern __shared__ char sm[];
    const u32 smb = smem_u32(sm);
    const int t  = threadIdx.x;
    const int w  = t>>5, ln = t&31;
    const int cta = blockIdx.x;
    const int d = cta>>6, r = cta&63;
    const int j0 = r<<4;
    const u32 mbW = smb+OFF_MB, mbH = smb+OFF_MB+8;

    if (t==0){
        MINIT(mbW,1); MINIT(mbH,1);
        MEXPECT(mbW, (u32)(WSLAB*2));
        BULK_G2S(smb+OFF_W, g_wh16 + (size_t)cta*WSLAB, (u32)(WSLAB*2), mbW);
    }

    // zero parity-0 h slabs (both dirs) + c state
    {
        u32* hz = (u32*)g_h16;              // parity0 = first 2*HSLAB halves
        for (int i = cta*256 + t; i < HSLAB; i += NB2*256) stcg_u32(hz+i, 0u);
    }
    float* cb = (float*)(sm + OFF_CB);
    cb[t] = 0.0f; cb[t+256] = 0.0f;
    __threadfence();
    gridbar();

    MWAIT(mbW, 0u);   // W slab resident from here on

    // ldmatrix lane address bases (byte offsets fixed; +2*k0 per k-step)
    const u32 aBase = smb + OFF_W + ((w>>1)*16 + (ln&15))*(WPAD*2) + ((ln>>4)<<4);
    const u32 bBase = smb + OFF_H + ((w&1)*16 + (ln&7) + ((ln>>4)<<3))*(WPAD*2)
                      + (((ln>>3)&1)<<4);
    float* gb = (float*)(sm + OFF_GB);      // 64 x 34

    for (int s=0; s<SEQ; s++){
        const int cur = s&1, nxt = cur^1;

        if (t==0){
            MEXPECT(mbH, (u32)(HSLAB*2));
            BULK_G2S(smb+OFF_H, g_h16 + (size_t)(cur*2+d)*HSLAB,
                     (u32)(HSLAB*2), mbH);
        }

        // xp prefetch for cell update: thread handles pairs p=t, t+256
        float xpv[2][4];
#pragma unroll
        for (int e=0;e<2;e++){
            const int p = t + (e<<8);
            const int u = p & 15, b = p >> 4;
            const float* xr = g_xp + ((size_t)d*M_TOT + (size_t)s*BATCH + b)*G4
                              + j0 + u;
#pragma unroll
            for (int q=0;q<4;q++) xpv[e][q] = ldcg1(xr + q*HID);
        }

        float acc[2][4] = {{0,0,0,0},{0,0,0,0}};
        MWAIT(mbH, (u32)(s&1));

#pragma unroll 4
        for (int k=0;k<64;k++){
            u32 a0,a1,a2,a3,b0,b1,b2,b3;
            ldsm4(a0,a1,a2,a3, aBase + (k<<5));
            ldsm4(b0,b1,b2,b3, bBase + (k<<5));
            mma16816(acc[0], a0,a1,a2,a3, b0,b1);
            mma16816(acc[1], a0,a1,a2,a3, b2,b3);
        }

        // write mma result to gbuf (row stride 34, col even -> aligned f2)
        {
            const int row0 = (w>>1)*16 + (ln>>2);
            const int col  = (w&1)*16 + ((ln&3)<<1);
#pragma unroll
            for (int nt=0; nt<2; nt++){
                float2 lo = make_float2(acc[nt][0], acc[nt][1]);
                float2 hi = make_float2(acc[nt][2], acc[nt][3]);
                *(float2*)&gb[ row0   *34 + col + nt*8] = lo;
                *(float2*)&gb[(row0+8)*34 + col + nt*8] = hi;
            }
        }
        __syncthreads();

        // fused cell update: 512 (u,b) pairs, 2 per thread
        const int sout = d ? (SEQ-1-s) : s;
        __half* hdst = g_h16 + (size_t)(nxt*2+d)*HSLAB;
#pragma unroll
        for (int e=0;e<2;e++){
            const int p = t + (e<<8);
            const int u = p & 15, b = p >> 4;
            float iv = gb[(    u)*34 + b] + xpv[e][0];
            float fv = gb[(16+u)*34 + b] + xpv[e][1];
            float gv = gb[(32+u)*34 + b] + xpv[e][2];
            float ov = gb[(48+u)*34 + b] + xpv[e][3];
            float c  = cb[p];
            c = sigf(fv)*c + sigf(iv)*tanhf(gv);
            float h = sigf(ov)*tanhf(c);
            cb[p] = c;
            out[((size_t)b*SEQ + sout)*(2*HID) + d*HID + j0 + u] = h;
            stcg16(hdst + (size_t)b*WPAD + j0 + u,
                   __half_as_ushort(__float2half_rn(h)));
        }
        __threadfence();
        gridbar();
    }
}

// ---------------- launcher -------------------------------------------------
extern "C" void kernel_launch(void* const* d_in, const int* in_sizes, int n_in,
                              void* d_out, int out_size)
{
    const float* x    = (const float*)d_in[0];
    const float* Wii  = (const float*)d_in[1];
    const float* Whi  = (const float*)d_in[2];
    const float* bi   = (const float*)d_in[3];
    const float* WiiR = (const float*)d_in[4];
    const float* WhiR = (const float*)d_in[5];
    const float* biR  = (const float*)d_in[6];
    float* out = (float*)d_out;

    cudaFuncSetAttribute(lstm_kernel,
        cudaFuncAttributeMaxDynamicSharedMemorySize, SMEM2L);

    wprep_kernel<<<128, 256>>>(Whi, WhiR);
    dim3 g1(G4/128, M_TOT/128, 2);
    xproj_kernel<<<g1, 256>>>(x, Wii, bi, WiiR, biR);
    lstm_kernel<<<NB2, 256, SMEM2L>>>(out);
}

// round 6
// speedup vs baseline: 17.3629x; 2.0076x over previous
#include <cuda_runtime.h>
#include <cuda_fp16.h>

typedef unsigned long long u64;
typedef unsigned int u32;

#define SEQ 512
#define BATCH 32
#define HID 1024
#define G4 4096
#define M_TOT 16384          /* SEQ*BATCH */
#define NB2 128              /* phase-2 persistent grid: 2 dirs x 64 */

#define WPAD 1048            /* lstm padded row length (halves) */
#define WSLAB (64*WPAD)
#define HSLAB (32*WPAD)

/* lstm smem byte offsets */
#define OFF_MB 0
#define OFF_W  1024
#define OFF_H  (OFF_W + 64*WPAD*2)
#define OFF_GB (OFF_H + 32*WPAD*2)
#define OFF_CB (OFF_GB + 64*34*4)
#define SMEM2L (OFF_CB + 512*4)

/* xproj mma smem: A/B tiles 128 rows x 40 halves (80B) = 10240B each,
   double buffered: buf stride 20480 */
#define XTP 10240
#define XBUF 20480
#define SMEMX (2*XBUF)

// scratch (device globals; no allocation allowed)
__device__ float  g_xp[(size_t)2 * M_TOT * G4];     // [dir][s*32+b][gate] fp32
__device__ __half g_wh16[(size_t)128 * WSLAB];      // lstm per-CTA W slabs
__device__ __half g_h16[4 * HSLAB];                 // [parity*2+dir][b][WPAD]
__device__ __half g_xh16[(size_t)M_TOT * HID];      // x in fp16 [b][s][k]
__device__ __half g_wi16[(size_t)2 * G4 * HID];     // W_ii fp16 [d][g][k]
__device__ u32 g_cnt;
__device__ u32 g_gen;

// ---------------- small helpers -------------------------------------------
__device__ __forceinline__ float sigf(float x){return 1.0f/(1.0f+__expf(-x));}
__device__ __forceinline__ float ldcg1(const float* p){
    float v;asm volatile("ld.global.cg.f32 %0,[%1];":"=f"(v):"l"(p));return v;}
__device__ __forceinline__ void stcg_u32(u32* p,u32 v){
    asm volatile("st.global.cg.u32 [%0],%1;"::"l"(p),"r"(v));}
__device__ __forceinline__ void stcg16(void* p,unsigned short v){
    asm volatile("st.global.cg.u16 [%0],%1;"::"l"(p),"h"(v));}
__device__ __forceinline__ u32 ldgen(){
    u32 v;asm volatile("ld.global.cg.u32 %0,[%1];":"=r"(v):"l"(&g_gen));return v;}
__device__ __forceinline__ u32 smem_u32(const void* p){
    u32 a;asm("{ .reg .u64 t; cvta.to.shared.u64 t, %1; cvt.u32.u64 %0, t; }":"=r"(a):"l"(p));return a;}

// ---------------- mbarrier / bulk / cp.async ------------------------------
#define MINIT(mb,cnt) asm volatile("mbarrier.init.shared.b64 [%0], %1;"::"r"(mb),"r"(cnt):"memory")
#define MEXPECT(mb,tx) asm volatile("mbarrier.arrive.expect_tx.shared.b64 _, [%0], %1;"::"r"(mb),"r"(tx):"memory")
#define MWAIT(mb,ph) do{ asm volatile("{\n\t.reg .pred P1;\n\tWL%=:\n\t" \
    "mbarrier.try_wait.parity.acquire.cta.shared::cta.b64 P1, [%0], %1, 0x989680;\n\t" \
    "@P1 bra WD%=;\n\tbra WL%=;\n\tWD%=:\n\t}" :: "r"(mb), "r"(ph) : "memory"); }while(0)
#define BULK_G2S(sm,gp,sz,mb) asm volatile( \
    "cp.async.bulk.shared::cta.global.mbarrier::complete_tx::bytes [%0], [%1], %2, [%3];" \
    ::"r"(sm),"l"(gp),"r"(sz),"r"(mb):"memory")
#define CP16(dst,src) asm volatile("cp.async.cg.shared.global [%0], [%1], 16;"::"r"(dst),"l"(src):"memory")
#define CPCOMMIT() asm volatile("cp.async.commit_group;":::"memory")
#define CPWAIT0()  asm volatile("cp.async.wait_group 0;":::"memory")

__device__ __forceinline__ void ldsm4(u32& r0,u32& r1,u32& r2,u32& r3,u32 a){
    asm volatile("ldmatrix.sync.aligned.m8n8.x4.shared.b16 {%0,%1,%2,%3},[%4];"
        :"=r"(r0),"=r"(r1),"=r"(r2),"=r"(r3):"r"(a));
}
__device__ __forceinline__ void mma16816(float* c,u32 a0,u32 a1,u32 a2,u32 a3,u32 b0,u32 b1){
    asm volatile("mma.sync.aligned.m16n8k16.row.col.f32.f16.f16.f32 "
        "{%0,%1,%2,%3},{%4,%5,%6,%7},{%8,%9},{%0,%1,%2,%3};"
        :"+f"(c[0]),"+f"(c[1]),"+f"(c[2]),"+f"(c[3])
        :"r"(a0),"r"(a1),"r"(a2),"r"(a3),"r"(b0),"r"(b1));
}

// ---------------- grid barrier (generation-based, replay-safe) ------------
__device__ __forceinline__ void gridbar(){
    __syncthreads();
    if (threadIdx.x==0){
        u32 my = ldgen();
        __threadfence();
        if (atomicAdd(&g_cnt,1u) == NB2-1u){
            atomicExch(&g_cnt,0u);
            __threadfence();
            atomicExch(&g_gen, my+1u);
        } else {
            while (ldgen()==my) __nanosleep(64);
        }
        __threadfence();
    }
    __syncthreads();
}

// ---------------- fp32 -> fp16 conversion (grid-stride, float4) -----------
__global__ __launch_bounds__(256) void conv_kernel(
    const float* __restrict__ src, __half* __restrict__ dst, int n4)
{
    int i = blockIdx.x*blockDim.x + threadIdx.x;
    int stride = gridDim.x*blockDim.x;
    for (; i<n4; i+=stride){
        float4 v = *(const float4*)(src + (size_t)i*4);
        __half2 h0 = __floats2half2_rn(v.x, v.y);
        __half2 h1 = __floats2half2_rn(v.z, v.w);
        u32* p = (u32*)(dst + (size_t)i*4);
        p[0] = *(u32*)&h0; p[1] = *(u32*)&h1;
    }
}

// ---------------- phase 0: W_hi -> fp16 padded per-CTA slabs --------------
__global__ __launch_bounds__(256) void wprep_kernel(
    const float* __restrict__ Whf, const float* __restrict__ Whr)
{
    const int c = blockIdx.x;
    const int d = c>>6, r = c&63, j0 = r<<4;
    const float* __restrict__ W = d ? Whr : Whf;
    __half* slab = g_wh16 + (size_t)c*WSLAB;

    const int t  = threadIdx.x;
    const int ri = t >> 2;
    const int k0 = (t & 3) << 8;
    const int grow = (ri>>4)*HID + j0 + (ri&15);
    const float* src = W + (size_t)grow*HID + k0;
    u32* dst = (u32*)(slab + ri*WPAD + k0);

#pragma unroll 8
    for (int k=0;k<256;k+=4){
        float4 v = *(const float4*)(src + k);
        __half2 h0 = __floats2half2_rn(v.x, v.y);
        __half2 h1 = __floats2half2_rn(v.z, v.w);
        dst[(k>>1)  ] = *(u32*)&h0;
        dst[(k>>1)+1] = *(u32*)&h1;
    }
}

// ---------------- phase 1: xp = x . W_ii^T + b  (fp16 mma.sync) -----------
// Tile 128x128, BK=32, 8 warps (wr=w>>2 in {0,1}: 64 m-rows; wc=w&3: 32 n).
// Warp tile 64x32: 4 m16 x 4 n8 frags. cp.async double-buffered.
__global__ __launch_bounds__(256,2) void xproj_mma_kernel(
    const float* __restrict__ bf, const float* __restrict__ br)
{
    extern __shared__ char xsm[];
    const u32 smb = smem_u32(xsm);
    const int t = threadIdx.x;
    const int w = t>>5, ln = t&31;
    const int d  = blockIdx.z;
    const int g0 = blockIdx.x << 7;
    const int m0 = blockIdx.y << 7;
    const float* __restrict__ bias = d ? br : bf;

    // per-thread staging: row r, two 16B chunks (cpc, cpc+1)
    const int r   = t & 127;
    const int cpc = (t>>7) << 1;
    const int m = m0 + r;
    const int s = m>>5, b = m&31;
    const int srow = d ? (SEQ-1-s) : s;
    const __half* aRow = g_xh16 + ((size_t)(b*SEQ + srow))*HID;
    const __half* bRow = g_wi16 + ((size_t)d*G4 + g0 + r)*HID;
    const u32 aDst = smb + r*80 + cpc*16;
    const u32 bDst = smb + XTP + r*80 + cpc*16;

    // ldmatrix lane bases
    const int wr = w>>2, wc = w&3;
    const u32 aL = smb + (wr*64 + (ln&15))*80 + ((ln>>4)<<4);
    const u32 bL = smb + XTP + (wc*32 + (ln&7) + ((ln>>4)<<3))*80
                   + (((ln>>3)&1)<<4);

    float acc[4][4][4];
#pragma unroll
    for (int i=0;i<4;i++)
#pragma unroll
        for (int j=0;j<4;j++)
#pragma unroll
            for (int q=0;q<4;q++) acc[i][j][q]=0.0f;

    // prologue: chunk 0 into buf 0
    CP16(aDst,      aRow + cpc*8);
    CP16(aDst+16,   aRow + cpc*8 + 8);
    CP16(bDst,      bRow + cpc*8);
    CP16(bDst+16,   bRow + cpc*8 + 8);
    CPCOMMIT();

    for (int c=0; c<32; c++){
        CPWAIT0();
        __syncthreads();
        if (c+1 < 32){
            const int kb = (c+1)*32;          // halves
            const u32 bo = ((c+1)&1)*XBUF;
            CP16(aDst+bo,    aRow + kb + cpc*8);
            CP16(aDst+bo+16, aRow + kb + cpc*8 + 8);
            CP16(bDst+bo,    bRow + kb + cpc*8);
            CP16(bDst+bo+16, bRow + kb + cpc*8 + 8);
            CPCOMMIT();
        }
        const u32 base = (c&1)*XBUF;
#pragma unroll
        for (int k16=0;k16<2;k16++){
            u32 aa[4][4], bb[2][4];
#pragma unroll
            for (int nt=0;nt<2;nt++)
                ldsm4(bb[nt][0],bb[nt][1],bb[nt][2],bb[nt][3],
                      bL + base + nt*1280 + k16*32);
#pragma unroll
            for (int mt=0;mt<4;mt++)
                ldsm4(aa[mt][0],aa[mt][1],aa[mt][2],aa[mt][3],
                      aL + base + mt*1280 + k16*32);
#pragma unroll
            for (int mt=0;mt<4;mt++){
#pragma unroll
                for (int nt=0;nt<2;nt++){
                    mma16816(acc[mt][nt*2  ], aa[mt][0],aa[mt][1],aa[mt][2],aa[mt][3],
                             bb[nt][0], bb[nt][1]);
                    mma16816(acc[mt][nt*2+1], aa[mt][0],aa[mt][1],aa[mt][2],aa[mt][3],
                             bb[nt][2], bb[nt][3]);
                }
            }
        }
    }

    // epilogue: add bias, write fp32 xp
    float2 bv[4];
#pragma unroll
    for (int n8=0;n8<4;n8++)
        bv[n8] = *(const float2*)&bias[g0 + wc*32 + n8*8 + (ln&3)*2];
#pragma unroll
    for (int mt=0;mt<4;mt++){
        const int r0 = m0 + wr*64 + mt*16 + (ln>>2);
        float* o0 = g_xp + ((size_t)d*M_TOT + r0    )*G4;
        float* o1 = g_xp + ((size_t)d*M_TOT + r0 + 8)*G4;
#pragma unroll
        for (int n8=0;n8<4;n8++){
            const int col = g0 + wc*32 + n8*8 + (ln&3)*2;
            *(float2*)(o0+col) = make_float2(acc[mt][n8][0]+bv[n8].x,
                                             acc[mt][n8][1]+bv[n8].y);
            *(float2*)(o1+col) = make_float2(acc[mt][n8][2]+bv[n8].x,
                                             acc[mt][n8][3]+bv[n8].y);
        }
    }
}

// ---------------- phase 2: persistent mma.sync recurrent kernel -----------
__global__ __launch_bounds__(256,1) void lstm_kernel(float* __restrict__ out)
{
    extern __shared__ char sm[];
    const u32 smb = smem_u32(sm);
    const int t  = threadIdx.x;
    const int w  = t>>5, ln = t&31;
    const int cta = blockIdx.x;
    const int d = cta>>6, r = cta&63;
    const int j0 = r<<4;
    const u32 mbW = smb+OFF_MB, mbH = smb+OFF_MB+8;

    if (t==0){
        MINIT(mbW,1); MINIT(mbH,1);
        MEXPECT(mbW, (u32)(WSLAB*2));
        BULK_G2S(smb+OFF_W, g_wh16 + (size_t)cta*WSLAB, (u32)(WSLAB*2), mbW);
    }

    {
        u32* hz = (u32*)g_h16;
        for (int i = cta*256 + t; i < HSLAB; i += NB2*256) stcg_u32(hz+i, 0u);
    }
    float* cb = (float*)(sm + OFF_CB);
    cb[t] = 0.0f; cb[t+256] = 0.0f;
    __threadfence();
    gridbar();

    MWAIT(mbW, 0u);

    const u32 aBase = smb + OFF_W + ((w>>1)*16 + (ln&15))*(WPAD*2) + ((ln>>4)<<4);
    const u32 bBase = smb + OFF_H + ((w&1)*16 + (ln&7) + ((ln>>4)<<3))*(WPAD*2)
                      + (((ln>>3)&1)<<4);
    float* gb = (float*)(sm + OFF_GB);

    for (int s=0; s<SEQ; s++){
        const int cur = s&1, nxt = cur^1;

        if (t==0){
            MEXPECT(mbH, (u32)(HSLAB*2));
            BULK_G2S(smb+OFF_H, g_h16 + (size_t)(cur*2+d)*HSLAB,
                     (u32)(HSLAB*2), mbH);
        }

        float xpv[2][4];
#pragma unroll
        for (int e=0;e<2;e++){
            const int p = t + (e<<8);
            const int u = p & 15, b = p >> 4;
            const float* xr = g_xp + ((size_t)d*M_TOT + (size_t)s*BATCH + b)*G4
                              + j0 + u;
#pragma unroll
            for (int q=0;q<4;q++) xpv[e][q] = ldcg1(xr + q*HID);
        }

        float acc[2][4] = {{0,0,0,0},{0,0,0,0}};
        MWAIT(mbH, (u32)(s&1));

#pragma unroll 4
        for (int k=0;k<64;k++){
            u32 a0,a1,a2,a3,b0,b1,b2,b3;
            ldsm4(a0,a1,a2,a3, aBase + (k<<5));
            ldsm4(b0,b1,b2,b3, bBase + (k<<5));
            mma16816(acc[0], a0,a1,a2,a3, b0,b1);
            mma16816(acc[1], a0,a1,a2,a3, b2,b3);
        }

        {
            const int row0 = (w>>1)*16 + (ln>>2);
            const int col  = (w&1)*16 + ((ln&3)<<1);
#pragma unroll
            for (int nt=0; nt<2; nt++){
                float2 lo = make_float2(acc[nt][0], acc[nt][1]);
                float2 hi = make_float2(acc[nt][2], acc[nt][3]);
                *(float2*)&gb[ row0   *34 + col + nt*8] = lo;
                *(float2*)&gb[(row0+8)*34 + col + nt*8] = hi;
            }
        }
        __syncthreads();

        const int sout = d ? (SEQ-1-s) : s;
        __half* hdst = g_h16 + (size_t)(nxt*2+d)*HSLAB;
#pragma unroll
        for (int e=0;e<2;e++){
            const int p = t + (e<<8);
            const int u = p & 15, b = p >> 4;
            float iv = gb[(    u)*34 + b] + xpv[e][0];
            float fv = gb[(16+u)*34 + b] + xpv[e][1];
            float gv = gb[(32+u)*34 + b] + xpv[e][2];
            float ov = gb[(48+u)*34 + b] + xpv[e][3];
            float c  = cb[p];
            c = sigf(fv)*c + sigf(iv)*tanhf(gv);
            float h = sigf(ov)*tanhf(c);
            cb[p] = c;
            out[((size_t)b*SEQ + sout)*(2*HID) + d*HID + j0 + u] = h;
            stcg16(hdst + (size_t)b*WPAD + j0 + u,
                   __half_as_ushort(__float2half_rn(h)));
        }
        __threadfence();
        gridbar();
    }
}

// ---------------- launcher -------------------------------------------------
extern "C" void kernel_launch(void* const* d_in, const int* in_sizes, int n_in,
                              void* d_out, int out_size)
{
    const float* x    = (const float*)d_in[0];
    const float* Wii  = (const float*)d_in[1];
    const float* Whi  = (const float*)d_in[2];
    const float* bi   = (const float*)d_in[3];
    const float* WiiR = (const float*)d_in[4];
    const float* WhiR = (const float*)d_in[5];
    const float* biR  = (const float*)d_in[6];
    float* out = (float*)d_out;

    cudaFuncSetAttribute(lstm_kernel,
        cudaFuncAttributeMaxDynamicSharedMemorySize, SMEM2L);
    cudaFuncSetAttribute(xproj_mma_kernel,
        cudaFuncAttributeMaxDynamicSharedMemorySize, SMEMX);

    // fp16 conversions
    __half* xh; cudaGetSymbolAddress((void**)&xh, g_xh16);
    __half* wi; cudaGetSymbolAddress((void**)&wi, g_wi16);
    conv_kernel<<<2048, 256>>>(x,    xh,                         M_TOT*HID/4);
    conv_kernel<<<1024, 256>>>(Wii,  wi,                         G4*HID/4);
    conv_kernel<<<1024, 256>>>(WiiR, wi + (size_t)G4*HID,        G4*HID/4);
    wprep_kernel<<<128, 256>>>(Whi, WhiR);

    dim3 g1(G4/128, M_TOT/128, 2);
    xproj_mma_kernel<<<g1, 256, SMEMX>>>(bi, biR);
    lstm_kernel<<<NB2, 256, SMEM2L>>>(out);
}

// round 7
// speedup vs baseline: 20.5944x; 1.1861x over previous
#include <cuda_runtime.h>
#include <cuda_fp16.h>

typedef unsigned long long u64;
typedef unsigned int u32;

#define SEQ 512
#define BATCH 32
#define HID 1024
#define G4 4096
#define M_TOT 16384          /* SEQ*BATCH */
#define NB2 128              /* phase-2 persistent grid: 2 dirs x 64 */

#define WPAD 1048            /* lstm padded row length (halves) */
#define WSLAB (64*WPAD)
#define HSLAB (32*WPAD)
#define HHALF (16*WPAD*2)    /* bytes per 16-batch half = 33536 */

/* lstm smem byte offsets */
#define OFF_MB 0             /* 3 mbarriers: W, H0, H1 */
#define OFF_W  1024
#define OFF_H  (OFF_W + 64*WPAD*2)       /* +134144 -> 135168 */
#define OFF_XS (OFF_H + 32*WPAD*2)       /* +67072  -> 202240 : xs2 128x20 f32 */
#define OFF_HS (OFF_XS + 128*20*4)       /* +10240  -> 212480 : hsout 16x33 f32 */
#define SMEM2L (OFF_HS + 16*33*4)        /* 214592 */

/* xproj mma smem: A/B tiles 128 rows x 40 halves (80B) = 10240B each,
   3-stage: buf stride 20480 */
#define XTP 10240
#define XBUF 20480
#define SMEMX (3*XBUF)

// scratch (device globals; no allocation allowed)
__device__ float  g_xp[(size_t)2 * M_TOT * G4];     // [dir][s*32+b][gate] fp32
__device__ __half g_wh16[(size_t)128 * WSLAB];      // lstm per-CTA W slabs
__device__ __half g_h16[4 * HSLAB];                 // [parity*2+dir][b][WPAD]
__device__ __half g_xh16[(size_t)M_TOT * HID];      // x in fp16 [b][s][k]
__device__ __half g_wi16[(size_t)2 * G4 * HID];     // W_ii fp16 [d][g][k]
__device__ u32 g_cnt;
__device__ u32 g_gen;

// ---------------- small helpers -------------------------------------------
__device__ __forceinline__ float sigf(float x){return 1.0f/(1.0f+__expf(-x));}
__device__ __forceinline__ void stcg_u32(u32* p,u32 v){
    asm volatile("st.global.cg.u32 [%0],%1;"::"l"(p),"r"(v));}
__device__ __forceinline__ void stcg_u64(void* p,u64 v){
    asm volatile("st.global.cg.u64 [%0],%1;"::"l"(p),"l"(v));}
__device__ __forceinline__ u32 smem_u32(const void* p){
    u32 a;asm("{ .reg .u64 t; cvta.to.shared.u64 t, %1; cvt.u32.u64 %0, t; }":"=r"(a):"l"(p));return a;}

// ---------------- mbarrier / bulk / cp.async ------------------------------
#define MINIT(mb,cnt) asm volatile("mbarrier.init.shared.b64 [%0], %1;"::"r"(mb),"r"(cnt):"memory")
#define MEXPECT(mb,tx) asm volatile("mbarrier.arrive.expect_tx.shared.b64 _, [%0], %1;"::"r"(mb),"r"(tx):"memory")
#define MWAIT(mb,ph) do{ asm volatile("{\n\t.reg .pred P1;\n\tWL%=:\n\t" \
    "mbarrier.try_wait.parity.acquire.cta.shared::cta.b64 P1, [%0], %1, 0x989680;\n\t" \
    "@P1 bra WD%=;\n\tbra WL%=;\n\tWD%=:\n\t}" :: "r"(mb), "r"(ph) : "memory"); }while(0)
#define BULK_G2S(sm,gp,sz,mb) asm volatile( \
    "cp.async.bulk.shared::cta.global.mbarrier::complete_tx::bytes [%0], [%1], %2, [%3];" \
    ::"r"(sm),"l"(gp),"r"(sz),"r"(mb):"memory")
#define CP16(dst,src) asm volatile("cp.async.cg.shared.global [%0], [%1], 16;"::"r"(dst),"l"(src):"memory")
#define CPCOMMIT() asm volatile("cp.async.commit_group;":::"memory")
#define CPWAIT0()  asm volatile("cp.async.wait_group 0;":::"memory")
#define CPWAIT1()  asm volatile("cp.async.wait_group 1;":::"memory")

__device__ __forceinline__ void ldsm4(u32& r0,u32& r1,u32& r2,u32& r3,u32 a){
    asm volatile("ldmatrix.sync.aligned.m8n8.x4.shared.b16 {%0,%1,%2,%3},[%4];"
        :"=r"(r0),"=r"(r1),"=r"(r2),"=r"(r3):"r"(a));
}
__device__ __forceinline__ void mma16816(float* c,u32 a0,u32 a1,u32 a2,u32 a3,u32 b0,u32 b1){
    asm volatile("mma.sync.aligned.m16n8k16.row.col.f32.f16.f16.f32 "
        "{%0,%1,%2,%3},{%4,%5,%6,%7},{%8,%9},{%0,%1,%2,%3};"
        :"+f"(c[0]),"+f"(c[1]),"+f"(c[2]),"+f"(c[3])
        :"r"(a0),"r"(a1),"r"(a2),"r"(a3),"r"(b0),"r"(b1));
}

// ---------------- grid barrier (release/acquire, reg-tracked gen) ---------
__device__ __forceinline__ void gridbar(u32& mygen){
    __syncthreads();
    if (threadIdx.x==0){
        u32 arr;
        asm volatile("atom.release.gpu.global.add.u32 %0,[%1],%2;"
                     :"=r"(arr):"l"(&g_cnt),"r"(1u));
        if (arr == NB2-1u){
            asm volatile("st.global.cg.u32 [%0],%1;"::"l"(&g_cnt),"r"(0u));
            asm volatile("st.release.gpu.global.u32 [%0],%1;"
                         ::"l"(&g_gen),"r"(mygen+1u));
        } else {
            u32 v;
            do { asm volatile("ld.acquire.gpu.global.u32 %0,[%1];"
                              :"=r"(v):"l"(&g_gen)); } while (v==mygen);
        }
    }
    mygen++;
    __syncthreads();
}

// ---------------- fp32 -> fp16 conversion (grid-stride, float4) -----------
__global__ __launch_bounds__(256) void conv_kernel(
    const float* __restrict__ src, __half* __restrict__ dst, int n4)
{
    int i = blockIdx.x*blockDim.x + threadIdx.x;
    int stride = gridDim.x*blockDim.x;
    for (; i<n4; i+=stride){
        float4 v = *(const float4*)(src + (size_t)i*4);
        __half2 h0 = __floats2half2_rn(v.x, v.y);
        __half2 h1 = __floats2half2_rn(v.z, v.w);
        u32* p = (u32*)(dst + (size_t)i*4);
        p[0] = *(u32*)&h0; p[1] = *(u32*)&h1;
    }
}

// ---------------- phase 0: W_hi -> fp16 gate-interleaved slabs ------------
// slab row ri = 16a + gate*4 + du  ->  gate row = gate*1024 + j0 + 4a + du
__global__ __launch_bounds__(256) void wprep_kernel(
    const float* __restrict__ Whf, const float* __restrict__ Whr)
{
    const int c = blockIdx.x;
    const int d = c>>6, r = c&63, j0 = r<<4;
    const float* __restrict__ W = d ? Whr : Whf;
    __half* slab = g_wh16 + (size_t)c*WSLAB;

    const int t  = threadIdx.x;
    const int ri = t >> 2;
    const int k0 = (t & 3) << 8;
    const int a = ri>>4, gate = (ri>>2)&3, du = ri&3;
    const int grow = gate*HID + j0 + a*4 + du;
    const float* src = W + (size_t)grow*HID + k0;
    u32* dst = (u32*)(slab + ri*WPAD + k0);

#pragma unroll 8
    for (int k=0;k<256;k+=4){
        float4 v = *(const float4*)(src + k);
        __half2 h0 = __floats2half2_rn(v.x, v.y);
        __half2 h1 = __floats2half2_rn(v.z, v.w);
        dst[(k>>1)  ] = *(u32*)&h0;
        dst[(k>>1)+1] = *(u32*)&h1;
    }
}

// ---------------- phase 1: xp = x . W_ii^T + b  (fp16 mma, 3-stage) -------
__global__ __launch_bounds__(256,2) void xproj_mma_kernel(
    const float* __restrict__ bf, const float* __restrict__ br)
{
    extern __shared__ char xsm[];
    const u32 smb = smem_u32(xsm);
    const int t = threadIdx.x;
    const int w = t>>5, ln = t&31;
    const int d  = blockIdx.z;
    const int g0 = blockIdx.x << 7;
    const int m0 = blockIdx.y << 7;
    const float* __restrict__ bias = d ? br : bf;

    const int r   = t & 127;
    const int cpc = (t>>7) << 1;
    const int m = m0 + r;
    const int s = m>>5, b = m&31;
    const int srow = d ? (SEQ-1-s) : s;
    const __half* aRow = g_xh16 + ((size_t)(b*SEQ + srow))*HID;
    const __half* bRow = g_wi16 + ((size_t)d*G4 + g0 + r)*HID;
    const u32 aDst = smb + r*80 + cpc*16;
    const u32 bDst = smb + XTP + r*80 + cpc*16;

    const int wr = w>>2, wc = w&3;
    const u32 aL = smb + (wr*64 + (ln&15))*80 + ((ln>>4)<<4);
    const u32 bL = smb + XTP + (wc*32 + (ln&7) + ((ln>>4)<<3))*80
                   + (((ln>>3)&1)<<4);

    float acc[4][4][4];
#pragma unroll
    for (int i=0;i<4;i++)
#pragma unroll
        for (int j=0;j<4;j++)
#pragma unroll
            for (int q=0;q<4;q++) acc[i][j][q]=0.0f;

    // prologue: chunks 0,1
#pragma unroll
    for (int pc=0;pc<2;pc++){
        const int kb = pc*32;
        const u32 bo = pc*XBUF;
        CP16(aDst+bo,    aRow + kb + cpc*8);
        CP16(aDst+bo+16, aRow + kb + cpc*8 + 8);
        CP16(bDst+bo,    bRow + kb + cpc*8);
        CP16(bDst+bo+16, bRow + kb + cpc*8 + 8);
        CPCOMMIT();
    }

    for (int c=0; c<32; c++){
        CPWAIT1();
        __syncthreads();
        if (c+2 < 32){
            const int kb = (c+2)*32;
            const u32 bo = ((c+2)%3)*XBUF;
            CP16(aDst+bo,    aRow + kb + cpc*8);
            CP16(aDst+bo+16, aRow + kb + cpc*8 + 8);
            CP16(bDst+bo,    bRow + kb + cpc*8);
            CP16(bDst+bo+16, bRow + kb + cpc*8 + 8);
        }
        CPCOMMIT();
        const u32 base = (c%3)*XBUF;
#pragma unroll
        for (int k16=0;k16<2;k16++){
            u32 aa[4][4], bb[2][4];
#pragma unroll
            for (int nt=0;nt<2;nt++)
                ldsm4(bb[nt][0],bb[nt][1],bb[nt][2],bb[nt][3],
                      bL + base + nt*1280 + k16*32);
#pragma unroll
            for (int mt=0;mt<4;mt++)
                ldsm4(aa[mt][0],aa[mt][1],aa[mt][2],aa[mt][3],
                      aL + base + mt*1280 + k16*32);
#pragma unroll
            for (int mt=0;mt<4;mt++){
#pragma unroll
                for (int nt=0;nt<2;nt++){
                    mma16816(acc[mt][nt*2  ], aa[mt][0],aa[mt][1],aa[mt][2],aa[mt][3],
                             bb[nt][0], bb[nt][1]);
                    mma16816(acc[mt][nt*2+1], aa[mt][0],aa[mt][1],aa[mt][2],aa[mt][3],
                             bb[nt][2], bb[nt][3]);
                }
            }
        }
    }

    float2 bv[4];
#pragma unroll
    for (int n8=0;n8<4;n8++)
        bv[n8] = *(const float2*)&bias[g0 + wc*32 + n8*8 + (ln&3)*2];
#pragma unroll
    for (int mt=0;mt<4;mt++){
        const int r0 = m0 + wr*64 + mt*16 + (ln>>2);
        float* o0 = g_xp + ((size_t)d*M_TOT + r0    )*G4;
        float* o1 = g_xp + ((size_t)d*M_TOT + r0 + 8)*G4;
#pragma unroll
        for (int n8=0;n8<4;n8++){
            const int col = g0 + wc*32 + n8*8 + (ln&3)*2;
            *(float2*)(o0+col) = make_float2(acc[mt][n8][0]+bv[n8].x,
                                             acc[mt][n8][1]+bv[n8].y);
            *(float2*)(o1+col) = make_float2(acc[mt][n8][2]+bv[n8].x,
                                             acc[mt][n8][3]+bv[n8].y);
        }
    }
}

// ---------------- phase 2: persistent mma.sync recurrent kernel -----------
// 128 CTAs = 2 dirs x 64. CTA owns 16 units -> 64 gate-interleaved rows.
// W slab resident in smem. Per step: h split-copy -> MMA -> reg epilogue
// (shfl gate exchange, c in regs) -> staged coalesced h/out stores.
__global__ __launch_bounds__(256,1) void lstm_kernel(float* __restrict__ out)
{
    extern __shared__ char sm[];
    const u32 smb = smem_u32(sm);
    const int t  = threadIdx.x;
    const int w  = t>>5, ln = t&31;
    const int cta = blockIdx.x;
    const int d = cta>>6, r = cta&63;
    const int j0 = r<<4;
    const u32 mbW = smb+OFF_MB, mbH0 = smb+OFF_MB+8, mbH1 = smb+OFF_MB+16;

    u32 bargen;
    asm volatile("ld.global.cg.u32 %0,[%1];":"=r"(bargen):"l"(&g_gen));

    if (t==0){
        MINIT(mbW,1); MINIT(mbH0,1); MINIT(mbH1,1);
        MEXPECT(mbW, (u32)(WSLAB*2));
        BULK_G2S(smb+OFF_W, g_wh16 + (size_t)cta*WSLAB, (u32)(WSLAB*2), mbW);
    }

    {   // zero parity-0 h slabs (both dirs)
        u32* hz = (u32*)g_h16;
        for (int i = cta*256 + t; i < HSLAB; i += NB2*256) stcg_u32(hz+i, 0u);
    }
    gridbar(bargen);

    MWAIT(mbW, 0u);

    const u32 aBase = smb + OFF_W + ((w>>1)*16 + (ln&15))*(WPAD*2) + ((ln>>4)<<4);
    const u32 bBase = smb + OFF_H + ((w&1)*16 + (ln&7) + ((ln>>4)<<3))*(WPAD*2)
                      + (((ln>>3)&1)<<4);
    const u32 myHmb = (w&1) ? mbH1 : mbH0;

    float* xs2   = (float*)(sm + OFF_XS);   // [(g*32+b)*20 + u]
    float* hsout = (float*)(sm + OFF_HS);   // [u*33 + b]

    // epilogue geometry
    const int q   = ln>>2;
    const int low = (q < 4);
    const int du  = q & 3;
    const int u   = ((w>>1)<<2) + du;       // unit 0..15
    const int col = ((w&1)<<4) + ((ln&3)<<1);
    const int c0i = low ? col : col+8;      // my two batch columns
    // xs cp.async geometry
    const int xb = t>>3, xg = (t&7)>>1, xh = (t&1);
    const u32 xsDst = smb + OFF_XS + ((xg*32+xb)*20 + xh*8)*4;

    float cst0 = 0.0f, cst1 = 0.0f;         // persistent cell state (regs)

    for (int s=0; s<SEQ; s++){
        const int cur = s&1, nxt = cur^1;

        if (t==0){
            const char* hsrc = (const char*)(g_h16 + (size_t)(cur*2+d)*HSLAB);
            MEXPECT(mbH0, (u32)HHALF);
            BULK_G2S(smb+OFF_H,         hsrc,         (u32)HHALF, mbH0);
            MEXPECT(mbH1, (u32)HHALF);
            BULK_G2S(smb+OFF_H+HHALF,   hsrc+HHALF,   (u32)HHALF, mbH1);
        }

        // stage xp for this step via cp.async (waited after MMA loop)
        {
            const float* xsrc = g_xp + ((size_t)d*M_TOT + (size_t)s*BATCH + xb)*G4
                               + xg*HID + j0 + xh*8;
            CP16(xsDst,    xsrc);
            CP16(xsDst+16, xsrc+4);
            CPCOMMIT();
        }

        float acc[2][4] = {{0,0,0,0},{0,0,0,0}};
        MWAIT(myHmb, (u32)(s&1));           // wait only my batch half

#pragma unroll 4
        for (int k=0;k<64;k++){
            u32 a0,a1,a2,a3,b0,b1,b2,b3;
            ldsm4(a0,a1,a2,a3, aBase + (k<<5));
            ldsm4(b0,b1,b2,b3, bBase + (k<<5));
            mma16816(acc[0], a0,a1,a2,a3, b0,b1);
            mma16816(acc[1], a0,a1,a2,a3, b2,b3);
        }

        CPWAIT0();   // xs2 ready (per-thread)
        // A = gate gA=q>>2 at cols {col,col+1,col+8,col+9}; B = gate gA+2
        const int gA = q>>2;                // 0 or 1
        float A0 = acc[0][0] + xs2[((gA  )*32 + col  )*20 + u];
        float A1 = acc[0][1] + xs2[((gA  )*32 + col+1)*20 + u];
        float A2 = acc[1][0] + xs2[((gA  )*32 + col+8)*20 + u];
        float A3 = acc[1][1] + xs2[((gA  )*32 + col+9)*20 + u];
        float B0 = acc[0][2] + xs2[((gA+2)*32 + col  )*20 + u];
        float B1 = acc[0][3] + xs2[((gA+2)*32 + col+1)*20 + u];
        float B2 = acc[1][2] + xs2[((gA+2)*32 + col+8)*20 + u];
        float B3 = acc[1][3] + xs2[((gA+2)*32 + col+9)*20 + u];

        // exchange with partner lane (ln ^ 16): send what partner needs
        float P0 = low ? A2 : A0;
        float P1 = low ? A3 : A1;
        float P2 = low ? B2 : B0;
        float P3 = low ? B3 : B1;
        P0 = __shfl_xor_sync(0xffffffffu, P0, 16);
        P1 = __shfl_xor_sync(0xffffffffu, P1, 16);
        P2 = __shfl_xor_sync(0xffffffffu, P2, 16);
        P3 = __shfl_xor_sync(0xffffffffu, P3, 16);

        float iv0 = low ? A0 : P0,  iv1 = low ? A1 : P1;
        float gv0 = low ? B0 : P2,  gv1 = low ? B1 : P3;
        float fv0 = low ? P0 : A2,  fv1 = low ? P1 : A3;
        float ov0 = low ? P2 : B2,  ov1 = low ? P3 : B3;

        cst0 = sigf(fv0)*cst0 + sigf(iv0)*tanhf(gv0);
        cst1 = sigf(fv1)*cst1 + sigf(iv1)*tanhf(gv1);
        float h0 = sigf(ov0)*tanhf(cst0);
        float h1 = sigf(ov1)*tanhf(cst1);
        hsout[u*33 + c0i    ] = h0;
        hsout[u*33 + c0i + 1] = h1;
        __syncthreads();

        // staged coalesced stores
        const int sout = d ? (SEQ-1-s) : s;
        if (t < 128){
            const int b = t>>2, u4 = (t&3)<<2;
            float4 v;
            v.x = hsout[(u4  )*33 + b];
            v.y = hsout[(u4+1)*33 + b];
            v.z = hsout[(u4+2)*33 + b];
            v.w = hsout[(u4+3)*33 + b];
            *(float4*)(out + ((size_t)b*SEQ + sout)*(2*HID) + d*HID + j0 + u4) = v;
        } else {
            const int t2 = t-128;
            const int b = t2>>2, u4 = (t2&3)<<2;
            __half2 ha = __floats2half2_rn(hsout[(u4  )*33+b], hsout[(u4+1)*33+b]);
            __half2 hb = __floats2half2_rn(hsout[(u4+2)*33+b], hsout[(u4+3)*33+b]);
            u64 pk = ((u64)(*(u32*)&hb) << 32) | (u64)(*(u32*)&ha);
            stcg_u64(g_h16 + (size_t)(nxt*2+d)*HSLAB + (size_t)b*WPAD + j0 + u4, pk);
        }
        gridbar(bargen);
    }
}

// ---------------- launcher -------------------------------------------------
extern "C" void kernel_launch(void* const* d_in, const int* in_sizes, int n_in,
                              void* d_out, int out_size)
{
    const float* x    = (const float*)d_in[0];
    const float* Wii  = (const float*)d_in[1];
    const float* Whi  = (const float*)d_in[2];
    const float* bi   = (const float*)d_in[3];
    const float* WiiR = (const float*)d_in[4];
    const float* WhiR = (const float*)d_in[5];
    const float* biR  = (const float*)d_in[6];
    float* out = (float*)d_out;

    cudaFuncSetAttribute(lstm_kernel,
        cudaFuncAttributeMaxDynamicSharedMemorySize, SMEM2L);
    cudaFuncSetAttribute(xproj_mma_kernel,
        cudaFuncAttributeMaxDynamicSharedMemorySize, SMEMX);

    __half* xh; cudaGetSymbolAddress((void**)&xh, g_xh16);
    __half* wi; cudaGetSymbolAddress((void**)&wi, g_wi16);
    conv_kernel<<<2048, 256>>>(x,    xh,                  M_TOT*HID/4);
    conv_kernel<<<1024, 256>>>(Wii,  wi,                  G4*HID/4);
    conv_kernel<<<1024, 256>>>(WiiR, wi + (size_t)G4*HID, G4*HID/4);
    wprep_kernel<<<128, 256>>>(Whi, WhiR);

    dim3 g1(G4/128, M_TOT/128, 2);
    xproj_mma_kernel<<<g1, 256, SMEMX>>>(bi, biR);
    lstm_kernel<<<NB2, 256, SMEM2L>>>(out);
}

// round 8
// speedup vs baseline: 21.5348x; 1.0457x over previous
#include <cuda_runtime.h>
#include <cuda_fp16.h>

typedef unsigned long long u64;
typedef unsigned int u32;

#define SEQ 512
#define BATCH 32
#define HID 1024
#define G4 4096
#define M_TOT 16384          /* SEQ*BATCH */
#define NB2 128              /* phase-2 persistent grid: 2 dirs x 64 */

#define WPAD 1048            /* lstm padded row length (halves) */
#define WSLAB (64*WPAD)
#define HSLAB (32*WPAD)
#define HHALF (16*WPAD*2)    /* bytes per 16-batch half = 33536 */

/* lstm smem byte offsets */
#define OFF_MB 0             /* 3 mbarriers: W, H0, H1 */
#define OFF_W  1024
#define OFF_H  (OFF_W + 64*WPAD*2)       /* +134144 -> 135168 */
#define OFF_XS (OFF_H + 32*WPAD*2)       /* +67072  -> 202240 : xs2 128x20 f32 */
#define OFF_HS (OFF_XS + 128*20*4)       /* +10240  -> 212480 : hsout 16x33 f32 */
#define SMEM2L (OFF_HS + 16*33*4)        /* 214592 */

/* xproj mma smem: A/B tiles 128 rows x 40 halves (80B) = 10240B each,
   3-stage: buf stride 20480 */
#define XTP 10240
#define XBUF 20480
#define SMEMX (3*XBUF)

// scratch (device globals; no allocation allowed)
__device__ float  g_xp[(size_t)2 * M_TOT * G4];     // [dir][s*32+b][gate] fp32
__device__ __half g_wh16[(size_t)128 * WSLAB];      // lstm per-CTA W slabs
__device__ __half g_h16[4 * HSLAB];                 // [parity*2+dir][b][WPAD]
__device__ __half g_xh16[(size_t)M_TOT * HID];      // x in fp16 [b][s][k]
__device__ __half g_wi16[(size_t)2 * G4 * HID];     // W_ii fp16 [d][g][k]
__device__ u32 g_cnt;
__device__ u32 g_gen;

// ---------------- fast activations (MUFU-only, ~2^-21 rel err) ------------
__device__ __forceinline__ float sigf(float x){
    return __fdividef(1.0f, 1.0f + __expf(-x));
}
__device__ __forceinline__ float tanhfast(float x){
    return 1.0f - __fdividef(2.0f, __expf(2.0f*x) + 1.0f);
}
__device__ __forceinline__ void stcg_u32(u32* p,u32 v){
    asm volatile("st.global.cg.u32 [%0],%1;"::"l"(p),"r"(v));}
__device__ __forceinline__ void stcg_u64(void* p,u64 v){
    asm volatile("st.global.cg.u64 [%0],%1;"::"l"(p),"l"(v));}
__device__ __forceinline__ u32 smem_u32(const void* p){
    u32 a;asm("{ .reg .u64 t; cvta.to.shared.u64 t, %1; cvt.u32.u64 %0, t; }":"=r"(a):"l"(p));return a;}

// ---------------- mbarrier / bulk / cp.async ------------------------------
#define MINIT(mb,cnt) asm volatile("mbarrier.init.shared.b64 [%0], %1;"::"r"(mb),"r"(cnt):"memory")
#define MEXPECT(mb,tx) asm volatile("mbarrier.arrive.expect_tx.shared.b64 _, [%0], %1;"::"r"(mb),"r"(tx):"memory")
#define MWAIT(mb,ph) do{ asm volatile("{\n\t.reg .pred P1;\n\tWL%=:\n\t" \
    "mbarrier.try_wait.parity.acquire.cta.shared::cta.b64 P1, [%0], %1, 0x989680;\n\t" \
    "@P1 bra WD%=;\n\tbra WL%=;\n\tWD%=:\n\t}" :: "r"(mb), "r"(ph) : "memory"); }while(0)
#define BULK_G2S(sm,gp,sz,mb) asm volatile( \
    "cp.async.bulk.shared::cta.global.mbarrier::complete_tx::bytes [%0], [%1], %2, [%3];" \
    ::"r"(sm),"l"(gp),"r"(sz),"r"(mb):"memory")
#define CP16(dst,src) asm volatile("cp.async.cg.shared.global [%0], [%1], 16;"::"r"(dst),"l"(src):"memory")
#define CPCOMMIT() asm volatile("cp.async.commit_group;":::"memory")
#define CPWAIT0()  asm volatile("cp.async.wait_group 0;":::"memory")
#define CPWAIT1()  asm volatile("cp.async.wait_group 1;":::"memory")

__device__ __forceinline__ void ldsm4(u32& r0,u32& r1,u32& r2,u32& r3,u32 a){
    asm volatile("ldmatrix.sync.aligned.m8n8.x4.shared.b16 {%0,%1,%2,%3},[%4];"
        :"=r"(r0),"=r"(r1),"=r"(r2),"=r"(r3):"r"(a));
}
__device__ __forceinline__ void mma16816(float* c,u32 a0,u32 a1,u32 a2,u32 a3,u32 b0,u32 b1){
    asm volatile("mma.sync.aligned.m16n8k16.row.col.f32.f16.f16.f32 "
        "{%0,%1,%2,%3},{%4,%5,%6,%7},{%8,%9},{%0,%1,%2,%3};"
        :"+f"(c[0]),"+f"(c[1]),"+f"(c[2]),"+f"(c[3])
        :"r"(a0),"r"(a1),"r"(a2),"r"(a3),"r"(b0),"r"(b1));
}

// ---------------- grid barrier (release/acquire, reg-tracked gen) ---------
__device__ __forceinline__ void gridbar(u32& mygen){
    __syncthreads();
    if (threadIdx.x==0){
        u32 arr;
        asm volatile("atom.release.gpu.global.add.u32 %0,[%1],%2;"
                     :"=r"(arr):"l"(&g_cnt),"r"(1u));
        if (arr == NB2-1u){
            asm volatile("st.global.cg.u32 [%0],%1;"::"l"(&g_cnt),"r"(0u));
            asm volatile("st.release.gpu.global.u32 [%0],%1;"
                         ::"l"(&g_gen),"r"(mygen+1u));
        } else {
            u32 v;
            do { asm volatile("ld.acquire.gpu.global.u32 %0,[%1];"
                              :"=r"(v):"l"(&g_gen)); } while (v==mygen);
        }
    }
    mygen++;
    __syncthreads();
}

// ---------------- fp32 -> fp16 conversion (grid-stride, float4) -----------
__global__ __launch_bounds__(256) void conv_kernel(
    const float* __restrict__ src, __half* __restrict__ dst, int n4)
{
    int i = blockIdx.x*blockDim.x + threadIdx.x;
    int stride = gridDim.x*blockDim.x;
    for (; i<n4; i+=stride){
        float4 v = *(const float4*)(src + (size_t)i*4);
        __half2 h0 = __floats2half2_rn(v.x, v.y);
        __half2 h1 = __floats2half2_rn(v.z, v.w);
        u32* p = (u32*)(dst + (size_t)i*4);
        p[0] = *(u32*)&h0; p[1] = *(u32*)&h1;
    }
}

// ---------------- phase 0: W_hi -> fp16 gate-interleaved slabs ------------
__global__ __launch_bounds__(256) void wprep_kernel(
    const float* __restrict__ Whf, const float* __restrict__ Whr)
{
    const int c = blockIdx.x;
    const int d = c>>6, r = c&63, j0 = r<<4;
    const float* __restrict__ W = d ? Whr : Whf;
    __half* slab = g_wh16 + (size_t)c*WSLAB;

    const int t  = threadIdx.x;
    const int ri = t >> 2;
    const int k0 = (t & 3) << 8;
    const int a = ri>>4, gate = (ri>>2)&3, du = ri&3;
    const int grow = gate*HID + j0 + a*4 + du;
    const float* src = W + (size_t)grow*HID + k0;
    u32* dst = (u32*)(slab + ri*WPAD + k0);

#pragma unroll 8
    for (int k=0;k<256;k+=4){
        float4 v = *(const float4*)(src + k);
        __half2 h0 = __floats2half2_rn(v.x, v.y);
        __half2 h1 = __floats2half2_rn(v.z, v.w);
        dst[(k>>1)  ] = *(u32*)&h0;
        dst[(k>>1)+1] = *(u32*)&h1;
    }
}

// ---------------- phase 1: xp = x . W_ii^T + b  (fp16 mma, 3-stage) -------
__global__ __launch_bounds__(256,2) void xproj_mma_kernel(
    const float* __restrict__ bf, const float* __restrict__ br)
{
    extern __shared__ char xsm[];
    const u32 smb = smem_u32(xsm);
    const int t = threadIdx.x;
    const int w = t>>5, ln = t&31;
    const int d  = blockIdx.z;
    const int g0 = blockIdx.x << 7;
    const int m0 = blockIdx.y << 7;
    const float* __restrict__ bias = d ? br : bf;

    const int r   = t & 127;
    const int cpc = (t>>7) << 1;
    const int m = m0 + r;
    const int s = m>>5, b = m&31;
    const int srow = d ? (SEQ-1-s) : s;
    const __half* aRow = g_xh16 + ((size_t)(b*SEQ + srow))*HID;
    const __half* bRow = g_wi16 + ((size_t)d*G4 + g0 + r)*HID;
    const u32 aDst = smb + r*80 + cpc*16;
    const u32 bDst = smb + XTP + r*80 + cpc*16;

    const int wr = w>>2, wc = w&3;
    const u32 aL = smb + (wr*64 + (ln&15))*80 + ((ln>>4)<<4);
    const u32 bL = smb + XTP + (wc*32 + (ln&7) + ((ln>>4)<<3))*80
                   + (((ln>>3)&1)<<4);

    float acc[4][4][4];
#pragma unroll
    for (int i=0;i<4;i++)
#pragma unroll
        for (int j=0;j<4;j++)
#pragma unroll
            for (int q=0;q<4;q++) acc[i][j][q]=0.0f;

#pragma unroll
    for (int pc=0;pc<2;pc++){
        const int kb = pc*32;
        const u32 bo = pc*XBUF;
        CP16(aDst+bo,    aRow + kb + cpc*8);
        CP16(aDst+bo+16, aRow + kb + cpc*8 + 8);
        CP16(bDst+bo,    bRow + kb + cpc*8);
        CP16(bDst+bo+16, bRow + kb + cpc*8 + 8);
        CPCOMMIT();
    }

    for (int c=0; c<32; c++){
        CPWAIT1();
        __syncthreads();
        if (c+2 < 32){
            const int kb = (c+2)*32;
            const u32 bo = ((c+2)%3)*XBUF;
            CP16(aDst+bo,    aRow + kb + cpc*8);
            CP16(aDst+bo+16, aRow + kb + cpc*8 + 8);
            CP16(bDst+bo,    bRow + kb + cpc*8);
            CP16(bDst+bo+16, bRow + kb + cpc*8 + 8);
        }
        CPCOMMIT();
        const u32 base = (c%3)*XBUF;
#pragma unroll
        for (int k16=0;k16<2;k16++){
            u32 aa[4][4], bb[2][4];
#pragma unroll
            for (int nt=0;nt<2;nt++)
                ldsm4(bb[nt][0],bb[nt][1],bb[nt][2],bb[nt][3],
                      bL + base + nt*1280 + k16*32);
#pragma unroll
            for (int mt=0;mt<4;mt++)
                ldsm4(aa[mt][0],aa[mt][1],aa[mt][2],aa[mt][3],
                      aL + base + mt*1280 + k16*32);
#pragma unroll
            for (int mt=0;mt<4;mt++){
#pragma unroll
                for (int nt=0;nt<2;nt++){
                    mma16816(acc[mt][nt*2  ], aa[mt][0],aa[mt][1],aa[mt][2],aa[mt][3],
                             bb[nt][0], bb[nt][1]);
                    mma16816(acc[mt][nt*2+1], aa[mt][0],aa[mt][1],aa[mt][2],aa[mt][3],
                             bb[nt][2], bb[nt][3]);
                }
            }
        }
    }

    float2 bv[4];
#pragma unroll
    for (int n8=0;n8<4;n8++)
        bv[n8] = *(const float2*)&bias[g0 + wc*32 + n8*8 + (ln&3)*2];
#pragma unroll
    for (int mt=0;mt<4;mt++){
        const int r0 = m0 + wr*64 + mt*16 + (ln>>2);
        float* o0 = g_xp + ((size_t)d*M_TOT + r0    )*G4;
        float* o1 = g_xp + ((size_t)d*M_TOT + r0 + 8)*G4;
#pragma unroll
        for (int n8=0;n8<4;n8++){
            const int col = g0 + wc*32 + n8*8 + (ln&3)*2;
            *(float2*)(o0+col) = make_float2(acc[mt][n8][0]+bv[n8].x,
                                             acc[mt][n8][1]+bv[n8].y);
            *(float2*)(o1+col) = make_float2(acc[mt][n8][2]+bv[n8].x,
                                             acc[mt][n8][3]+bv[n8].y);
        }
    }
}

// ---------------- phase 2: persistent mma.sync recurrent kernel -----------
__global__ __launch_bounds__(256,1) void lstm_kernel(float* __restrict__ out)
{
    extern __shared__ char sm[];
    const u32 smb = smem_u32(sm);
    const int t  = threadIdx.x;
    const int w  = t>>5, ln = t&31;
    const int cta = blockIdx.x;
    const int d = cta>>6, r = cta&63;
    const int j0 = r<<4;
    const u32 mbW = smb+OFF_MB, mbH0 = smb+OFF_MB+8, mbH1 = smb+OFF_MB+16;

    u32 bargen;
    asm volatile("ld.global.cg.u32 %0,[%1];":"=r"(bargen):"l"(&g_gen));

    if (t==0){
        MINIT(mbW,1); MINIT(mbH0,1); MINIT(mbH1,1);
        MEXPECT(mbW, (u32)(WSLAB*2));
        BULK_G2S(smb+OFF_W, g_wh16 + (size_t)cta*WSLAB, (u32)(WSLAB*2), mbW);
    }

    {
        u32* hz = (u32*)g_h16;
        for (int i = cta*256 + t; i < HSLAB; i += NB2*256) stcg_u32(hz+i, 0u);
    }
    gridbar(bargen);

    MWAIT(mbW, 0u);

    const u32 aBase = smb + OFF_W + ((w>>1)*16 + (ln&15))*(WPAD*2) + ((ln>>4)<<4);
    const u32 bBase = smb + OFF_H + ((w&1)*16 + (ln&7) + ((ln>>4)<<3))*(WPAD*2)
                      + (((ln>>3)&1)<<4);
    const u32 myHmb = (w&1) ? mbH1 : mbH0;

    float* xs2   = (float*)(sm + OFF_XS);
    float* hsout = (float*)(sm + OFF_HS);

    const int q   = ln>>2;
    const int low = (q < 4);
    const int du  = q & 3;
    const int u   = ((w>>1)<<2) + du;
    const int col = ((w&1)<<4) + ((ln&3)<<1);
    const int c0i = low ? col : col+8;
    const int xb = t>>3, xg = (t&7)>>1, xh = (t&1);
    const u32 xsDst = smb + OFF_XS + ((xg*32+xb)*20 + xh*8)*4;

    float cst0 = 0.0f, cst1 = 0.0f;

    for (int s=0; s<SEQ; s++){
        const int cur = s&1, nxt = cur^1;

        if (t==0){
            const char* hsrc = (const char*)(g_h16 + (size_t)(cur*2+d)*HSLAB);
            MEXPECT(mbH0, (u32)HHALF);
            BULK_G2S(smb+OFF_H,         hsrc,         (u32)HHALF, mbH0);
            MEXPECT(mbH1, (u32)HHALF);
            BULK_G2S(smb+OFF_H+HHALF,   hsrc+HHALF,   (u32)HHALF, mbH1);
        }

        {
            const float* xsrc = g_xp + ((size_t)d*M_TOT + (size_t)s*BATCH + xb)*G4
                               + xg*HID + j0 + xh*8;
            CP16(xsDst,    xsrc);
            CP16(xsDst+16, xsrc+4);
            CPCOMMIT();
        }

        float acc[2][4] = {{0,0,0,0},{0,0,0,0}};
        MWAIT(myHmb, (u32)(s&1));

        // software-pipelined MMA loop: prefetch k+1 frags before computing k
        u32 a0,a1,a2,a3,b0,b1,b2,b3;
        ldsm4(a0,a1,a2,a3, aBase);
        ldsm4(b0,b1,b2,b3, bBase);
#pragma unroll 7
        for (int k=0;k<63;k++){
            u32 na0,na1,na2,na3,nb0,nb1,nb2,nb3;
            ldsm4(na0,na1,na2,na3, aBase + ((k+1)<<5));
            ldsm4(nb0,nb1,nb2,nb3, bBase + ((k+1)<<5));
            mma16816(acc[0], a0,a1,a2,a3, b0,b1);
            mma16816(acc[1], a0,a1,a2,a3, b2,b3);
            a0=na0;a1=na1;a2=na2;a3=na3;
            b0=nb0;b1=nb1;b2=nb2;b3=nb3;
        }
        mma16816(acc[0], a0,a1,a2,a3, b0,b1);
        mma16816(acc[1], a0,a1,a2,a3, b2,b3);

        CPWAIT0();
        const int gA = q>>2;
        float A0 = acc[0][0] + xs2[((gA  )*32 + col  )*20 + u];
        float A1 = acc[0][1] + xs2[((gA  )*32 + col+1)*20 + u];
        float A2 = acc[1][0] + xs2[((gA  )*32 + col+8)*20 + u];
        float A3 = acc[1][1] + xs2[((gA  )*32 + col+9)*20 + u];
        float B0 = acc[0][2] + xs2[((gA+2)*32 + col  )*20 + u];
        float B1 = acc[0][3] + xs2[((gA+2)*32 + col+1)*20 + u];
        float B2 = acc[1][2] + xs2[((gA+2)*32 + col+8)*20 + u];
        float B3 = acc[1][3] + xs2[((gA+2)*32 + col+9)*20 + u];

        float P0 = low ? A2 : A0;
        float P1 = low ? A3 : A1;
        float P2 = low ? B2 : B0;
        float P3 = low ? B3 : B1;
        P0 = __shfl_xor_sync(0xffffffffu, P0, 16);
        P1 = __shfl_xor_sync(0xffffffffu, P1, 16);
        P2 = __shfl_xor_sync(0xffffffffu, P2, 16);
        P3 = __shfl_xor_sync(0xffffffffu, P3, 16);

        float iv0 = low ? A0 : P0,  iv1 = low ? A1 : P1;
        float gv0 = low ? B0 : P2,  gv1 = low ? B1 : P3;
        float fv0 = low ? P0 : A2,  fv1 = low ? P1 : A3;
        float ov0 = low ? P2 : B2,  ov1 = low ? P3 : B3;

        cst0 = sigf(fv0)*cst0 + sigf(iv0)*tanhfast(gv0);
        cst1 = sigf(fv1)*cst1 + sigf(iv1)*tanhfast(gv1);
        float h0 = sigf(ov0)*tanhfast(cst0);
        float h1 = sigf(ov1)*tanhfast(cst1);
        hsout[u*33 + c0i    ] = h0;
        hsout[u*33 + c0i + 1] = h1;
        __syncthreads();

        const int sout = d ? (SEQ-1-s) : s;
        if (t < 128){
            const int b = t>>2, u4 = (t&3)<<2;
            float4 v;
            v.x = hsout[(u4  )*33 + b];
            v.y = hsout[(u4+1)*33 + b];
            v.z = hsout[(u4+2)*33 + b];
            v.w = hsout[(u4+3)*33 + b];
            *(float4*)(out + ((size_t)b*SEQ + sout)*(2*HID) + d*HID + j0 + u4) = v;
        } else {
            const int t2 = t-128;
            const int b = t2>>2, u4 = (t2&3)<<2;
            __half2 ha = __floats2half2_rn(hsout[(u4  )*33+b], hsout[(u4+1)*33+b]);
            __half2 hb = __floats2half2_rn(hsout[(u4+2)*33+b], hsout[(u4+3)*33+b]);
            u64 pk = ((u64)(*(u32*)&hb) << 32) | (u64)(*(u32*)&ha);
            stcg_u64(g_h16 + (size_t)(nxt*2+d)*HSLAB + (size_t)b*WPAD + j0 + u4, pk);
        }
        gridbar(bargen);
    }
}

// ---------------- launcher -------------------------------------------------
extern "C" void kernel_launch(void* const* d_in, const int* in_sizes, int n_in,
                              void* d_out, int out_size)
{
    const float* x    = (const float*)d_in[0];
    const float* Wii  = (const float*)d_in[1];
    const float* Whi  = (const float*)d_in[2];
    const float* bi   = (const float*)d_in[3];
    const float* WiiR = (const float*)d_in[4];
    const float* WhiR = (const float*)d_in[5];
    const float* biR  = (const float*)d_in[6];
    float* out = (float*)d_out;

    cudaFuncSetAttribute(lstm_kernel,
        cudaFuncAttributeMaxDynamicSharedMemorySize, SMEM2L);
    cudaFuncSetAttribute(xproj_mma_kernel,
        cudaFuncAttributeMaxDynamicSharedMemorySize, SMEMX);

    __half* xh; cudaGetSymbolAddress((void**)&xh, g_xh16);
    __half* wi; cudaGetSymbolAddress((void**)&wi, g_wi16);
    conv_kernel<<<2048, 256>>>(x,    xh,                  M_TOT*HID/4);
    conv_kernel<<<1024, 256>>>(Wii,  wi,                  G4*HID/4);
    conv_kernel<<<1024, 256>>>(WiiR, wi + (size_t)G4*HID, G4*HID/4);
    wprep_kernel<<<128, 256>>>(Whi, WhiR);

    dim3 g1(G4/128, M_TOT/128, 2);
    xproj_mma_kernel<<<g1, 256, SMEMX>>>(bi, biR);
    lstm_kernel<<<NB2, 256, SMEM2L>>>(out);
}

// round 9
// speedup vs baseline: 23.1947x; 1.0771x over previous
#include <cuda_runtime.h>
#include <cuda_fp16.h>

typedef unsigned long long u64;
typedef unsigned int u32;

#define SEQ 512
#define BATCH 32
#define HID 1024
#define G4 4096
#define M_TOT 16384          /* SEQ*BATCH */
#define NB2 128              /* phase-2 persistent grid: 2 dirs x 64 */

#define WPAD 1048            /* lstm padded row length (halves) */
#define WSLAB (64*WPAD)
#define HSLAB (32*WPAD)
#define HHALF (16*WPAD*2)    /* bytes per 16-batch half = 33536 */

/* lstm smem byte offsets */
#define OFF_MB 0             /* 3 mbarriers: W, H0, H1 */
#define OFF_W  1024
#define OFF_H  (OFF_W + 64*WPAD*2)       /* +134144 -> 135168 */
#define OFF_XS (OFF_H + 32*WPAD*2)       /* +67072  -> 202240 : xs2 128x20 f32 */
#define OFF_HS (OFF_XS + 128*20*4)       /* +10240  -> 212480 : hsout 16x33 f32 */
#define SMEM2L (OFF_HS + 16*33*4)        /* 214592 */

/* xproj mma smem */
#define XTP 10240
#define XBUF 20480
#define SMEMX (3*XBUF)

// scratch (device globals; no allocation allowed)
__device__ float  g_xp[(size_t)2 * M_TOT * G4];     // [dir][s*32+b][gate] fp32
__device__ __half g_wh16[(size_t)128 * WSLAB];      // lstm per-CTA W slabs
__device__ __half g_h16[4 * HSLAB];                 // [parity*2+dir][b][WPAD]
__device__ __half g_xh16[(size_t)M_TOT * HID];      // x in fp16 [b][s][k]
__device__ __half g_wi16[(size_t)2 * G4 * HID];     // W_ii fp16 [d][g][k]
__device__ u32 g_cnt;
__device__ u32 g_gen;
__device__ u32 g_prod[2][2][32];    // [dir][parity][pad] monotonic produced
__device__ u32 g_cons[2][2][32];    // [dir][parity][pad] monotonic consumed

// ---------------- fast activations (MUFU-only) ----------------------------
__device__ __forceinline__ float sigf(float x){
    return __fdividef(1.0f, 1.0f + __expf(-x));
}
__device__ __forceinline__ float tanhfast(float x){
    return 1.0f - __fdividef(2.0f, __expf(2.0f*x) + 1.0f);
}
__device__ __forceinline__ void stcg_u32(u32* p,u32 v){
    asm volatile("st.global.cg.u32 [%0],%1;"::"l"(p),"r"(v));}
__device__ __forceinline__ void stcg_u64(void* p,u64 v){
    asm volatile("st.global.cg.u64 [%0],%1;"::"l"(p),"l"(v));}
__device__ __forceinline__ u32 ldcgu(const u32* p){
    u32 v;asm volatile("ld.global.cg.u32 %0,[%1];":"=r"(v):"l"(p));return v;}
__device__ __forceinline__ u32 smem_u32(const void* p){
    u32 a;asm("{ .reg .u64 t; cvta.to.shared.u64 t, %1; cvt.u32.u64 %0, t; }":"=r"(a):"l"(p));return a;}
__device__ __forceinline__ void red_rel(u32* p){
    asm volatile("red.release.gpu.global.add.u32 [%0],%1;"::"l"(p),"r"(1u):"memory");}
__device__ __forceinline__ void spin_ge(const u32* p,u32 tgt){
    u32 v;
    do { asm volatile("ld.acquire.gpu.global.u32 %0,[%1];":"=r"(v):"l"(p)); }
    while ((int)(v - tgt) < 0);
}

// ---------------- mbarrier / bulk / cp.async ------------------------------
#define MINIT(mb,cnt) asm volatile("mbarrier.init.shared.b64 [%0], %1;"::"r"(mb),"r"(cnt):"memory")
#define MEXPECT(mb,tx) asm volatile("mbarrier.arrive.expect_tx.shared.b64 _, [%0], %1;"::"r"(mb),"r"(tx):"memory")
#define MWAIT(mb,ph) do{ asm volatile("{\n\t.reg .pred P1;\n\tWL%=:\n\t" \
    "mbarrier.try_wait.parity.acquire.cta.shared::cta.b64 P1, [%0], %1, 0x989680;\n\t" \
    "@P1 bra WD%=;\n\tbra WL%=;\n\tWD%=:\n\t}" :: "r"(mb), "r"(ph) : "memory"); }while(0)
#define BULK_G2S(sm,gp,sz,mb) asm volatile( \
    "cp.async.bulk.shared::cta.global.mbarrier::complete_tx::bytes [%0], [%1], %2, [%3];" \
    ::"r"(sm),"l"(gp),"r"(sz),"r"(mb):"memory")
#define CP16(dst,src) asm volatile("cp.async.cg.shared.global [%0], [%1], 16;"::"r"(dst),"l"(src):"memory")
#define CPCOMMIT() asm volatile("cp.async.commit_group;":::"memory")
#define CPWAIT0()  asm volatile("cp.async.wait_group 0;":::"memory")
#define CPWAIT1()  asm volatile("cp.async.wait_group 1;":::"memory")

__device__ __forceinline__ void ldsm4(u32& r0,u32& r1,u32& r2,u32& r3,u32 a){
    asm volatile("ldmatrix.sync.aligned.m8n8.x4.shared.b16 {%0,%1,%2,%3},[%4];"
        :"=r"(r0),"=r"(r1),"=r"(r2),"=r"(r3):"r"(a));
}
__device__ __forceinline__ void mma16816(float* c,u32 a0,u32 a1,u32 a2,u32 a3,u32 b0,u32 b1){
    asm volatile("mma.sync.aligned.m16n8k16.row.col.f32.f16.f16.f32 "
        "{%0,%1,%2,%3},{%4,%5,%6,%7},{%8,%9},{%0,%1,%2,%3};"
        :"+f"(c[0]),"+f"(c[1]),"+f"(c[2]),"+f"(c[3])
        :"r"(a0),"r"(a1),"r"(a2),"r"(a3),"r"(b0),"r"(b1));
}

// ---------------- init-only grid barrier ----------------------------------
__device__ __forceinline__ void gridbar(u32& mygen){
    __syncthreads();
    if (threadIdx.x==0){
        u32 arr;
        asm volatile("atom.release.gpu.global.add.u32 %0,[%1],%2;"
                     :"=r"(arr):"l"(&g_cnt),"r"(1u));
        if (arr == NB2-1u){
            asm volatile("st.global.cg.u32 [%0],%1;"::"l"(&g_cnt),"r"(0u));
            asm volatile("st.release.gpu.global.u32 [%0],%1;"
                         ::"l"(&g_gen),"r"(mygen+1u));
        } else {
            u32 v;
            do { asm volatile("ld.acquire.gpu.global.u32 %0,[%1];"
                              :"=r"(v):"l"(&g_gen)); } while (v==mygen);
        }
    }
    mygen++;
    __syncthreads();
}

// ---------------- fp32 -> fp16 conversion ---------------------------------
__global__ __launch_bounds__(256) void conv_kernel(
    const float* __restrict__ src, __half* __restrict__ dst, int n4)
{
    int i = blockIdx.x*blockDim.x + threadIdx.x;
    int stride = gridDim.x*blockDim.x;
    for (; i<n4; i+=stride){
        float4 v = *(const float4*)(src + (size_t)i*4);
        __half2 h0 = __floats2half2_rn(v.x, v.y);
        __half2 h1 = __floats2half2_rn(v.z, v.w);
        u32* p = (u32*)(dst + (size_t)i*4);
        p[0] = *(u32*)&h0; p[1] = *(u32*)&h1;
    }
}

// ---------------- phase 0: W_hi -> fp16 gate-interleaved slabs ------------
__global__ __launch_bounds__(256) void wprep_kernel(
    const float* __restrict__ Whf, const float* __restrict__ Whr)
{
    const int c = blockIdx.x;
    const int d = c>>6, r = c&63, j0 = r<<4;
    const float* __restrict__ W = d ? Whr : Whf;
    __half* slab = g_wh16 + (size_t)c*WSLAB;

    const int t  = threadIdx.x;
    const int ri = t >> 2;
    const int k0 = (t & 3) << 8;
    const int a = ri>>4, gate = (ri>>2)&3, du = ri&3;
    const int grow = gate*HID + j0 + a*4 + du;
    const float* src = W + (size_t)grow*HID + k0;
    u32* dst = (u32*)(slab + ri*WPAD + k0);

#pragma unroll 8
    for (int k=0;k<256;k+=4){
        float4 v = *(const float4*)(src + k);
        __half2 h0 = __floats2half2_rn(v.x, v.y);
        __half2 h1 = __floats2half2_rn(v.z, v.w);
        dst[(k>>1)  ] = *(u32*)&h0;
        dst[(k>>1)+1] = *(u32*)&h1;
    }
}

// ---------------- phase 1: xp = x . W_ii^T + b  (fp16 mma, 3-stage) -------
__global__ __launch_bounds__(256,2) void xproj_mma_kernel(
    const float* __restrict__ bf, const float* __restrict__ br)
{
    extern __shared__ char xsm[];
    const u32 smb = smem_u32(xsm);
    const int t = threadIdx.x;
    const int w = t>>5, ln = t&31;
    const int d  = blockIdx.z;
    const int g0 = blockIdx.x << 7;
    const int m0 = blockIdx.y << 7;
    const float* __restrict__ bias = d ? br : bf;

    const int r   = t & 127;
    const int cpc = (t>>7) << 1;
    const int m = m0 + r;
    const int s = m>>5, b = m&31;
    const int srow = d ? (SEQ-1-s) : s;
    const __half* aRow = g_xh16 + ((size_t)(b*SEQ + srow))*HID;
    const __half* bRow = g_wi16 + ((size_t)d*G4 + g0 + r)*HID;
    const u32 aDst = smb + r*80 + cpc*16;
    const u32 bDst = smb + XTP + r*80 + cpc*16;

    const int wr = w>>2, wc = w&3;
    const u32 aL = smb + (wr*64 + (ln&15))*80 + ((ln>>4)<<4);
    const u32 bL = smb + XTP + (wc*32 + (ln&7) + ((ln>>4)<<3))*80
                   + (((ln>>3)&1)<<4);

    float acc[4][4][4];
#pragma unroll
    for (int i=0;i<4;i++)
#pragma unroll
        for (int j=0;j<4;j++)
#pragma unroll
            for (int q=0;q<4;q++) acc[i][j][q]=0.0f;

#pragma unroll
    for (int pc=0;pc<2;pc++){
        const int kb = pc*32;
        const u32 bo = pc*XBUF;
        CP16(aDst+bo,    aRow + kb + cpc*8);
        CP16(aDst+bo+16, aRow + kb + cpc*8 + 8);
        CP16(bDst+bo,    bRow + kb + cpc*8);
        CP16(bDst+bo+16, bRow + kb + cpc*8 + 8);
        CPCOMMIT();
    }

    for (int c=0; c<32; c++){
        CPWAIT1();
        __syncthreads();
        if (c+2 < 32){
            const int kb = (c+2)*32;
            const u32 bo = ((c+2)%3)*XBUF;
            CP16(aDst+bo,    aRow + kb + cpc*8);
            CP16(aDst+bo+16, aRow + kb + cpc*8 + 8);
            CP16(bDst+bo,    bRow + kb + cpc*8);
            CP16(bDst+bo+16, bRow + kb + cpc*8 + 8);
        }
        CPCOMMIT();
        const u32 base = (c%3)*XBUF;
#pragma unroll
        for (int k16=0;k16<2;k16++){
            u32 aa[4][4], bb[2][4];
#pragma unroll
            for (int nt=0;nt<2;nt++)
                ldsm4(bb[nt][0],bb[nt][1],bb[nt][2],bb[nt][3],
                      bL + base + nt*1280 + k16*32);
#pragma unroll
            for (int mt=0;mt<4;mt++)
                ldsm4(aa[mt][0],aa[mt][1],aa[mt][2],aa[mt][3],
                      aL + base + mt*1280 + k16*32);
#pragma unroll
            for (int mt=0;mt<4;mt++){
#pragma unroll
                for (int nt=0;nt<2;nt++){
                    mma16816(acc[mt][nt*2  ], aa[mt][0],aa[mt][1],aa[mt][2],aa[mt][3],
                             bb[nt][0], bb[nt][1]);
                    mma16816(acc[mt][nt*2+1], aa[mt][0],aa[mt][1],aa[mt][2],aa[mt][3],
                             bb[nt][2], bb[nt][3]);
                }
            }
        }
    }

    float2 bv[4];
#pragma unroll
    for (int n8=0;n8<4;n8++)
        bv[n8] = *(const float2*)&bias[g0 + wc*32 + n8*8 + (ln&3)*2];
#pragma unroll
    for (int mt=0;mt<4;mt++){
        const int r0 = m0 + wr*64 + mt*16 + (ln>>2);
        float* o0 = g_xp + ((size_t)d*M_TOT + r0    )*G4;
        float* o1 = g_xp + ((size_t)d*M_TOT + r0 + 8)*G4;
#pragma unroll
        for (int n8=0;n8<4;n8++){
            const int col = g0 + wc*32 + n8*8 + (ln&3)*2;
            *(float2*)(o0+col) = make_float2(acc[mt][n8][0]+bv[n8].x,
                                             acc[mt][n8][1]+bv[n8].y);
            *(float2*)(o1+col) = make_float2(acc[mt][n8][2]+bv[n8].x,
                                             acc[mt][n8][3]+bv[n8].y);
        }
    }
}

// ---------------- phase 2: persistent mma.sync recurrent kernel -----------
// Flag-based direction-local sync (no per-step grid barrier):
//   produced[d][p]: +1 per CTA per h-write round of parity p (release)
//   consumed[d][p]: +2 per CTA per h-read round (one per half, release)
__global__ __launch_bounds__(256,1) void lstm_kernel(float* __restrict__ out)
{
    extern __shared__ char sm[];
    const u32 smb = smem_u32(sm);
    const int t  = threadIdx.x;
    const int w  = t>>5, ln = t&31;
    const int cta = blockIdx.x;
    const int d = cta>>6, r = cta&63;
    const int j0 = r<<4;
    const u32 mbW = smb+OFF_MB, mbH0 = smb+OFF_MB+8, mbH1 = smb+OFF_MB+16;

    u32 bargen;
    asm volatile("ld.global.cg.u32 %0,[%1];":"=r"(bargen):"l"(&g_gen));

    // per-launch flag baselines (read BEFORE the init barrier => quiescent)
    u32 pBase0=0,pBase1=0,cBase0=0,cBase1=0;
    if (t==0){
        pBase0 = ldcgu(&g_prod[d][0][0]); pBase1 = ldcgu(&g_prod[d][1][0]);
        cBase0 = ldcgu(&g_cons[d][0][0]); cBase1 = ldcgu(&g_cons[d][1][0]);
    }

    if (t==0){
        MINIT(mbW,1); MINIT(mbH0,1); MINIT(mbH1,1);
        MEXPECT(mbW, (u32)(WSLAB*2));
        BULK_G2S(smb+OFF_W, g_wh16 + (size_t)cta*WSLAB, (u32)(WSLAB*2), mbW);
    }

    {
        u32* hz = (u32*)g_h16;
        for (int i = cta*256 + t; i < HSLAB; i += NB2*256) stcg_u32(hz+i, 0u);
    }
    gridbar(bargen);

    MWAIT(mbW, 0u);

    const u32 aBase = smb + OFF_W + ((w>>1)*16 + (ln&15))*(WPAD*2) + ((ln>>4)<<4);
    const u32 bBase = smb + OFF_H + ((w&1)*16 + (ln&7) + ((ln>>4)<<3))*(WPAD*2)
                      + (((ln>>3)&1)<<4);
    const u32 myHmb = (w&1) ? mbH1 : mbH0;

    float* xs2   = (float*)(sm + OFF_XS);
    float* hsout = (float*)(sm + OFF_HS);

    const int q   = ln>>2;
    const int low = (q < 4);
    const int du  = q & 3;
    const int u   = ((w>>1)<<2) + du;
    const int col = ((w&1)<<4) + ((ln&3)<<1);
    const int c0i = low ? col : col+8;
    const int xb = t>>3, xg = (t&7)>>1, xh = (t&1);
    const u32 xsDst = smb + OFF_XS + ((xg*32+xb)*20 + xh*8)*4;

    float cst0 = 0.0f, cst1 = 0.0f;

    for (int s=0; s<SEQ; s++){
        const int cur = s&1, nxt = cur^1;
        const u32 rnd = (u32)((s+1)>>1);

        if (t==0){
            // wait h(s) produced (parity cur), then pull both halves
            spin_ge(&g_prod[d][cur][0], (cur?pBase1:pBase0) + 64u*rnd);
            const char* hsrc = (const char*)(g_h16 + (size_t)(cur*2+d)*HSLAB);
            MEXPECT(mbH0, (u32)HHALF);
            BULK_G2S(smb+OFF_H,         hsrc,         (u32)HHALF, mbH0);
            MEXPECT(mbH1, (u32)HHALF);
            BULK_G2S(smb+OFF_H+HHALF,   hsrc+HHALF,   (u32)HHALF, mbH1);
        }

        {
            const float* xsrc = g_xp + ((size_t)d*M_TOT + (size_t)s*BATCH + xb)*G4
                               + xg*HID + j0 + xh*8;
            CP16(xsDst,    xsrc);
            CP16(xsDst+16, xsrc+4);
            CPCOMMIT();
        }

        float acc[2][4] = {{0,0,0,0},{0,0,0,0}};
        MWAIT(myHmb, (u32)(s&1));
        // per-half consumed signal: global h buffer (parity cur) read done
        if (ln==0 && w<2) red_rel(&g_cons[d][cur][0]);

        u32 a0,a1,a2,a3,b0,b1,b2,b3;
        ldsm4(a0,a1,a2,a3, aBase);
        ldsm4(b0,b1,b2,b3, bBase);
#pragma unroll 7
        for (int k=0;k<63;k++){
            u32 na0,na1,na2,na3,nb0,nb1,nb2,nb3;
            ldsm4(na0,na1,na2,na3, aBase + ((k+1)<<5));
            ldsm4(nb0,nb1,nb2,nb3, bBase + ((k+1)<<5));
            mma16816(acc[0], a0,a1,a2,a3, b0,b1);
            mma16816(acc[1], a0,a1,a2,a3, b2,b3);
            a0=na0;a1=na1;a2=na2;a3=na3;
            b0=nb0;b1=nb1;b2=nb2;b3=nb3;
        }
        mma16816(acc[0], a0,a1,a2,a3, b0,b1);
        mma16816(acc[1], a0,a1,a2,a3, b2,b3);

        CPWAIT0();
        const int gA = q>>2;
        float A0 = acc[0][0] + xs2[((gA  )*32 + col  )*20 + u];
        float A1 = acc[0][1] + xs2[((gA  )*32 + col+1)*20 + u];
        float A2 = acc[1][0] + xs2[((gA  )*32 + col+8)*20 + u];
        float A3 = acc[1][1] + xs2[((gA  )*32 + col+9)*20 + u];
        float B0 = acc[0][2] + xs2[((gA+2)*32 + col  )*20 + u];
        float B1 = acc[0][3] + xs2[((gA+2)*32 + col+1)*20 + u];
        float B2 = acc[1][2] + xs2[((gA+2)*32 + col+8)*20 + u];
        float B3 = acc[1][3] + xs2[((gA+2)*32 + col+9)*20 + u];

        float P0 = low ? A2 : A0;
        float P1 = low ? A3 : A1;
        float P2 = low ? B2 : B0;
        float P3 = low ? B3 : B1;
        P0 = __shfl_xor_sync(0xffffffffu, P0, 16);
        P1 = __shfl_xor_sync(0xffffffffu, P1, 16);
        P2 = __shfl_xor_sync(0xffffffffu, P2, 16);
        P3 = __shfl_xor_sync(0xffffffffu, P3, 16);

        float iv0 = low ? A0 : P0,  iv1 = low ? A1 : P1;
        float gv0 = low ? B0 : P2,  gv1 = low ? B1 : P3;
        float fv0 = low ? P0 : A2,  fv1 = low ? P1 : A3;
        float ov0 = low ? P2 : B2,  ov1 = low ? P3 : B3;

        cst0 = sigf(fv0)*cst0 + sigf(iv0)*tanhfast(gv0);
        cst1 = sigf(fv1)*cst1 + sigf(iv1)*tanhfast(gv1);
        float h0 = sigf(ov0)*tanhfast(cst0);
        float h1 = sigf(ov1)*tanhfast(cst1);
        hsout[u*33 + c0i    ] = h0;
        hsout[u*33 + c0i + 1] = h1;

        // before overwriting global h parity nxt: all reads of that parity done
        if (t==0 && s>0)
            spin_ge(&g_cons[d][nxt][0], (nxt?cBase1:cBase0) + 128u*rnd);
        __syncthreads();

        const int sout = d ? (SEQ-1-s) : s;
        if (t < 128){
            const int b = t>>2, u4 = (t&3)<<2;
            float4 v;
            v.x = hsout[(u4  )*33 + b];
            v.y = hsout[(u4+1)*33 + b];
            v.z = hsout[(u4+2)*33 + b];
            v.w = hsout[(u4+3)*33 + b];
            *(float4*)(out + ((size_t)b*SEQ + sout)*(2*HID) + d*HID + j0 + u4) = v;
        } else {
            const int t2 = t-128;
            const int b = t2>>2, u4 = (t2&3)<<2;
            __half2 ha = __floats2half2_rn(hsout[(u4  )*33+b], hsout[(u4+1)*33+b]);
            __half2 hb = __floats2half2_rn(hsout[(u4+2)*33+b], hsout[(u4+3)*33+b]);
            u64 pk = ((u64)(*(u32*)&hb) << 32) | (u64)(*(u32*)&ha);
            stcg_u64(g_h16 + (size_t)(nxt*2+d)*HSLAB + (size_t)b*WPAD + j0 + u4, pk);
        }
        __syncthreads();
        if (t==0) red_rel(&g_prod[d][nxt][0]);   // h(s+1) published
    }
}

// ---------------- launcher -------------------------------------------------
extern "C" void kernel_launch(void* const* d_in, const int* in_sizes, int n_in,
                              void* d_out, int out_size)
{
    const float* x    = (const float*)d_in[0];
    const float* Wii  = (const float*)d_in[1];
    const float* Whi  = (const float*)d_in[2];
    const float* bi   = (const float*)d_in[3];
    const float* WiiR = (const float*)d_in[4];
    const float* WhiR = (const float*)d_in[5];
    const float* biR  = (const float*)d_in[6];
    float* out = (float*)d_out;

    cudaFuncSetAttribute(lstm_kernel,
        cudaFuncAttributeMaxDynamicSharedMemorySize, SMEM2L);
    cudaFuncSetAttribute(xproj_mma_kernel,
        cudaFuncAttributeMaxDynamicSharedMemorySize, SMEMX);

    __half* xh; cudaGetSymbolAddress((void**)&xh, g_xh16);
    __half* wi; cudaGetSymbolAddress((void**)&wi, g_wi16);
    conv_kernel<<<2048, 256>>>(x,    xh,                  M_TOT*HID/4);
    conv_kernel<<<1024, 256>>>(Wii,  wi,                  G4*HID/4);
    conv_kernel<<<1024, 256>>>(WiiR, wi + (size_t)G4*HID, G4*HID/4);
    wprep_kernel<<<128, 256>>>(Whi, WhiR);

    dim3 g1(G4/128, M_TOT/128, 2);
    xproj_mma_kernel<<<g1, 256, SMEMX>>>(bi, biR);
    lstm_kernel<<<NB2, 256, SMEM2L>>>(out);
}